// round 1
// baseline (speedup 1.0000x reference)
#include <cuda_runtime.h>
#include <cstdint>

// ---------------------------------------------------------------------------
// MinkUNet forward on GB300.
// Per layer: conv_bn_kernel (gather-spconv + per-block BN partial sums)
//            finalize_kernel (32 threads: scale/shift from sums)
//            apply_kernel    (y = relu(x*scale+shift [+res]))
// ---------------------------------------------------------------------------

typedef unsigned long long u64;

#define MAXN 450000
__device__ float g_bufA[(size_t)MAXN * 32];
__device__ float g_bufB[(size_t)MAXN * 32];
__device__ float g_bufC[(size_t)MAXN * 32];
__device__ float g_bufD[(size_t)MAXN * 32];
__device__ float g_stats[7 * 64];   // per layer: sum[32], sumsq[32]
__device__ float g_ss[7 * 64];      // per layer: scale[32], shift[32]

__device__ __forceinline__ void ffma2(u64 &acc, u64 a, u64 b) {
    asm volatile("fma.rn.f32x2 %0, %1, %2, %0;" : "+l"(acc) : "l"(a), "l"(b));
}
__device__ __forceinline__ u64 pack2(float x) {
    u64 r;
    asm("mov.b64 %0, {%1, %1};" : "=l"(r) : "r"(__float_as_uint(x)));
    return r;
}

// One ci step: acc[0..15] (f32x2 pairs = 32 output channels) += fv * W[ci][:]
__device__ __forceinline__ void ci_step(u64 *acc, const ulonglong2 *w, float fv) {
    u64 ff = pack2(fv);
#pragma unroll
    for (int j = 0; j < 8; j++) {
        ulonglong2 ww = w[j];           // LDS.128 broadcast (conflict-free)
        ffma2(acc[2 * j],     ff, ww.x);
        ffma2(acc[2 * j + 1], ff, ww.y);
    }
}

template <int K, int CI>
__global__ void __launch_bounds__(256, 2) conv_bn_kernel(
    const float *__restrict__ feat,   // [*, CI] gathered by nbr indices
    const int   *__restrict__ nbr,    // [K, N]
    const float *__restrict__ W,      // [K, CI, 32]
    float       *__restrict__ out,    // [N, 32]
    float       *__restrict__ stats,  // [64] global accumulators
    int N)
{
    extern __shared__ float smemW[];  // K*CI*32 floats
    __shared__ float s_sum[64];

    int tid = threadIdx.x;
#pragma unroll 1
    for (int i = tid; i < K * CI * 8; i += 256)
        ((float4 *)smemW)[i] = ((const float4 *)W)[i];
    if (tid < 64) s_sum[tid] = 0.f;
    __syncthreads();

    int r = blockIdx.x * 256 + tid;

    u64 acc[16];
#pragma unroll
    for (int i = 0; i < 16; i++) acc[i] = 0ULL;

    if (r < N) {
        int idx = __ldg(&nbr[r]);  // k = 0
#pragma unroll 1
        for (int k = 0; k < K; k++) {
            // prefetch next tap's index to hide L2 latency
            int nidx = (k + 1 < K) ? __ldg(&nbr[(size_t)(k + 1) * N + r]) : -1;
            if (idx >= 0) {
                const float4 *f4 = (const float4 *)(feat + (size_t)idx * CI);
                float4 fr[CI / 4];
#pragma unroll
                for (int j = 0; j < CI / 4; j++) fr[j] = __ldg(f4 + j);
                const ulonglong2 *wk = (const ulonglong2 *)(smemW + k * CI * 32);
#pragma unroll
                for (int j4 = 0; j4 < CI / 4; j4++) {
                    float4 f = fr[j4];
                    ci_step(acc, wk + (4 * j4 + 0) * 8, f.x);
                    ci_step(acc, wk + (4 * j4 + 1) * 8, f.y);
                    ci_step(acc, wk + (4 * j4 + 2) * 8, f.z);
                    ci_step(acc, wk + (4 * j4 + 3) * 8, f.w);
                }
            }
            idx = nidx;
        }
        // write output row (raw pre-BN)
        float4 *o = (float4 *)(out + (size_t)r * 32);
#pragma unroll
        for (int j = 0; j < 8; j++) {
            float2 a = *(float2 *)&acc[2 * j];
            float2 b = *(float2 *)&acc[2 * j + 1];
            o[j] = make_float4(a.x, a.y, b.x, b.y);
        }
    }

    // BN partial sums: warp butterfly per channel, then shared, then global
#pragma unroll
    for (int c = 0; c < 32; c++) {
        float2 p = *(float2 *)&acc[c >> 1];
        float s = (c & 1) ? p.y : p.x;
        float q = s * s;
#pragma unroll
        for (int o = 16; o > 0; o >>= 1) {
            s += __shfl_xor_sync(0xffffffffu, s, o);
            q += __shfl_xor_sync(0xffffffffu, q, o);
        }
        if ((tid & 31) == 0) {
            atomicAdd(&s_sum[c], s);
            atomicAdd(&s_sum[32 + c], q);
        }
    }
    __syncthreads();
    if (tid < 64) atomicAdd(&stats[tid], s_sum[tid]);
}

__global__ void finalize_kernel(const float *__restrict__ stats,
                                const float *__restrict__ gamma,
                                const float *__restrict__ beta,
                                float *__restrict__ ss, float invN)
{
    int c = threadIdx.x;  // 32 threads
    float mu  = stats[c] * invN;
    float var = stats[32 + c] * invN - mu * mu;
    float s = rsqrtf(var + 1e-5f) * gamma[c];
    ss[c] = s;
    ss[32 + c] = beta[c] - mu * s;
}

__global__ void apply_kernel(const float *__restrict__ x,
                             const float *__restrict__ ss,
                             const float *__restrict__ res,
                             float *__restrict__ out, int n4)
{
    int i = blockIdx.x * blockDim.x + threadIdx.x;
    if (i >= n4) return;
    int j = i & 7;
    float4 v  = ((const float4 *)x)[i];
    float4 sc = ((const float4 *)ss)[j];
    float4 sh = ((const float4 *)ss)[8 + j];
    float4 o;
    o.x = fmaf(v.x, sc.x, sh.x);
    o.y = fmaf(v.y, sc.y, sh.y);
    o.z = fmaf(v.z, sc.z, sh.z);
    o.w = fmaf(v.w, sc.w, sh.w);
    if (res) {
        float4 rr = ((const float4 *)res)[i];
        o.x += rr.x; o.y += rr.y; o.z += rr.z; o.w += rr.w;
    }
    o.x = fmaxf(o.x, 0.f);
    o.y = fmaxf(o.y, 0.f);
    o.z = fmaxf(o.z, 0.f);
    o.w = fmaxf(o.w, 0.f);
    ((float4 *)out)[i] = o;
}

__global__ void zero_kernel(float *p, int n)
{
    int i = blockIdx.x * blockDim.x + threadIdx.x;
    if (i < n) p[i] = 0.f;
}

extern "C" void kernel_launch(void *const *d_in, const int *in_sizes, int n_in,
                              void *d_out, int out_size)
{
    const float *vf     = (const float *)d_in[0];
    const float *Wstem1 = (const float *)d_in[1];
    const float *Wstem2 = (const float *)d_in[2];
    const float *Wdown  = (const float *)d_in[3];
    const float *Wr1a   = (const float *)d_in[4];
    const float *Wr1b   = (const float *)d_in[5];
    const float *Wr2a   = (const float *)d_in[6];
    const float *Wr2b   = (const float *)d_in[7];
    const float *gammas = (const float *)d_in[8];
    const float *betas  = (const float *)d_in[9];
    const int *nbr0  = (const int *)d_in[10];
    const int *down1 = (const int *)d_in[11];
    const int *nbr1  = (const int *)d_in[12];

    int N0 = in_sizes[10] / 27;
    int N1 = in_sizes[11] / 8;

    float *bufA, *bufB, *bufC, *bufD, *stats, *ss;
    cudaGetSymbolAddress((void **)&bufA, g_bufA);
    cudaGetSymbolAddress((void **)&bufB, g_bufB);
    cudaGetSymbolAddress((void **)&bufC, g_bufC);
    cudaGetSymbolAddress((void **)&bufD, g_bufD);
    cudaGetSymbolAddress((void **)&stats, g_stats);
    cudaGetSymbolAddress((void **)&ss, g_ss);

    size_t sm27_32 = (size_t)27 * 32 * 32 * sizeof(float);   // 110592
    size_t sm27_4  = (size_t)27 * 4 * 32 * sizeof(float);    // 13824
    size_t sm8_32  = (size_t)8 * 32 * 32 * sizeof(float);    // 32768
    cudaFuncSetAttribute(conv_bn_kernel<27, 32>,
                         cudaFuncAttributeMaxDynamicSharedMemorySize,
                         (int)sm27_32);

    int g0 = (N0 + 255) / 256;
    int g1 = (N1 + 255) / 256;
    int a0 = (N0 * 8 + 255) / 256;
    int a1 = (N1 * 8 + 255) / 256;
    float invN0 = 1.f / (float)N0;
    float invN1 = 1.f / (float)N1;
    float *out = (float *)d_out;

    zero_kernel<<<1, 448>>>(stats, 448);

    // stem1: CBR(vf, nbr0, W_stem1)
    conv_bn_kernel<27, 4><<<g0, 256, sm27_4>>>(vf, nbr0, Wstem1, bufA, stats + 0, N0);
    finalize_kernel<<<1, 32>>>(stats + 0, gammas + 0, betas + 0, ss + 0, invN0);
    apply_kernel<<<a0, 256>>>(bufA, ss + 0, nullptr, bufB, N0 * 8);

    // stem2
    conv_bn_kernel<27, 32><<<g0, 256, sm27_32>>>(bufB, nbr0, Wstem2, bufA, stats + 64, N0);
    finalize_kernel<<<1, 32>>>(stats + 64, gammas + 32, betas + 32, ss + 64, invN0);
    apply_kernel<<<a0, 256>>>(bufA, ss + 64, nullptr, bufB, N0 * 8);

    // down: K=8, input level-0 (bufB), output level-1
    conv_bn_kernel<8, 32><<<g1, 256, sm8_32>>>(bufB, down1, Wdown, bufC, stats + 128, N1);
    finalize_kernel<<<1, 32>>>(stats + 128, gammas + 64, betas + 64, ss + 128, invN1);
    apply_kernel<<<a1, 256>>>(bufC, ss + 128, nullptr, bufD, N1 * 8);   // bufD = x1

    // res block 1
    conv_bn_kernel<27, 32><<<g1, 256, sm27_32>>>(bufD, nbr1, Wr1a, bufC, stats + 192, N1);
    finalize_kernel<<<1, 32>>>(stats + 192, gammas + 96, betas + 96, ss + 192, invN1);
    apply_kernel<<<a1, 256>>>(bufC, ss + 192, nullptr, bufA, N1 * 8);   // h

    conv_bn_kernel<27, 32><<<g1, 256, sm27_32>>>(bufA, nbr1, Wr1b, bufC, stats + 256, N1);
    finalize_kernel<<<1, 32>>>(stats + 256, gammas + 128, betas + 128, ss + 256, invN1);
    apply_kernel<<<a1, 256>>>(bufC, ss + 256, bufD, bufB, N1 * 8);      // bufB = x1'

    // res block 2
    conv_bn_kernel<27, 32><<<g1, 256, sm27_32>>>(bufB, nbr1, Wr2a, bufC, stats + 320, N1);
    finalize_kernel<<<1, 32>>>(stats + 320, gammas + 160, betas + 160, ss + 320, invN1);
    apply_kernel<<<a1, 256>>>(bufC, ss + 320, nullptr, bufA, N1 * 8);   // h

    conv_bn_kernel<27, 32><<<g1, 256, sm27_32>>>(bufA, nbr1, Wr2b, bufC, stats + 384, N1);
    finalize_kernel<<<1, 32>>>(stats + 384, gammas + 192, betas + 192, ss + 384, invN1);
    apply_kernel<<<a1, 256>>>(bufC, ss + 384, bufB, out, N1 * 8);       // final output
}

// round 3
// speedup vs baseline: 1.8322x; 1.8322x over previous
#include <cuda_runtime.h>
#include <cuda_bf16.h>
#include <cstdint>

typedef unsigned long long u64;
typedef unsigned int u32;

// ---------------------------------------------------------------------------
// Scratch (no allocations allowed)
// ---------------------------------------------------------------------------
#define MAXN 450000
__device__ float g_bufA[(size_t)MAXN * 32];
__device__ float g_bufB[(size_t)MAXN * 32];
__device__ float g_bufC[(size_t)MAXN * 32];
__device__ float g_bufD[(size_t)MAXN * 32];
__device__ float g_stats[7 * 64];   // per layer: sum[32], sumsq[32]
__device__ float g_ss[7 * 64];      // per layer: scale[32], shift[32]
// Fragment-ordered split-bf16 weights:
// per layer: hi[K*512 u32] then lo[K*512 u32]. 5 layers K=27 + 1 layer K=8.
__device__ u32 g_Bw[5 * 27 * 1024 + 8 * 1024];

// ---------------------------------------------------------------------------
// helpers
// ---------------------------------------------------------------------------
__device__ __forceinline__ u32 smem_to_u32(const void *p) {
    u32 a;
    asm("{ .reg .u64 t; cvta.to.shared.u64 t, %1; cvt.u32.u64 %0, t; }"
        : "=r"(a) : "l"(p));
    return a;
}
// pack: low half <- a, high half <- b
__device__ __forceinline__ u32 packbf(float a, float b) {
    u32 r;
    asm("cvt.rn.bf16x2.f32 %0, %1, %2;" : "=r"(r) : "f"(b), "f"(a));
    return r;
}
__device__ __forceinline__ float lof(u32 h) { return __uint_as_float(h << 16); }
__device__ __forceinline__ float hif(u32 h) { return __uint_as_float(h & 0xFFFF0000u); }

__device__ __forceinline__ void ldsm4(u32 *r, u32 addr) {
    asm volatile("ldmatrix.sync.aligned.m8n8.x4.shared.b16 {%0,%1,%2,%3}, [%4];"
                 : "=r"(r[0]), "=r"(r[1]), "=r"(r[2]), "=r"(r[3]) : "r"(addr));
}
__device__ __forceinline__ void sts128(u32 addr, u32 a, u32 b, u32 c, u32 d) {
    asm volatile("st.shared.v4.b32 [%0], {%1,%2,%3,%4};"
                 :: "r"(addr), "r"(a), "r"(b), "r"(c), "r"(d) : "memory");
}
__device__ __forceinline__ void mma16816(float *d, const u32 *a, u32 b0, u32 b1) {
    asm volatile(
        "mma.sync.aligned.m16n8k16.row.col.f32.bf16.bf16.f32 "
        "{%0,%1,%2,%3}, {%4,%5,%6,%7}, {%8,%9}, {%0,%1,%2,%3};"
        : "+f"(d[0]), "+f"(d[1]), "+f"(d[2]), "+f"(d[3])
        : "r"(a[0]), "r"(a[1]), "r"(a[2]), "r"(a[3]), "r"(b0), "r"(b1));
}

// ---------------------------------------------------------------------------
// Weight prep: W[k][ci][co] fp32 -> per-thread fragment order.
// For mma m16n8k16 col-major B: thread t holds
//   b0 = (k=kc*16+2c+0/1, n=nc*8+t/4), b1 = (k=kc*16+2c+8+0/1, n)
// hi layout: [tap][kc][lane][nc][j]  (512 u32/tap); lo at +K*512.
// ---------------------------------------------------------------------------
__global__ void prep_weights(const float *__restrict__ W, u32 *__restrict__ out, int K)
{
    int t = blockIdx.x * 256 + threadIdx.x;
    if (t >= K * 512) return;
    int r    = t & 511;
    int tap  = t >> 9;
    int kc   = r >> 8;
    int r2   = r & 255;
    int lane = r2 >> 3;
    int nc   = (r2 >> 1) & 3;
    int j    = r2 & 1;
    int k0   = kc * 16 + (lane & 3) * 2 + j * 8;
    int n    = nc * 8 + (lane >> 2);
    float w0 = W[((size_t)tap * 32 + k0) * 32 + n];
    float w1 = W[((size_t)tap * 32 + k0 + 1) * 32 + n];
    u32 h = packbf(w0, w1);
    u32 l = packbf(w0 - lof(h), w1 - hif(h));
    out[t] = h;
    out[(size_t)K * 512 + t] = l;
}

// ---------------------------------------------------------------------------
// HMMA gather-spconv + BN partial sums.
// 128 rows / CTA (16 per warp), 256 threads. Warp-local pipeline.
// ---------------------------------------------------------------------------
template <int K>
__global__ void __launch_bounds__(256, 2) mma_conv_kernel(
    const float *__restrict__ feat,   // [*, 32]
    const int   *__restrict__ nbr,    // [K, N]
    const uint4 *__restrict__ Wf,     // fragment-ordered weights (hi then lo)
    float       *__restrict__ out,    // [N, 32] raw pre-BN
    float       *__restrict__ stats,  // [64]
    int N)
{
    // [warp][stage*2 + (hi=0/lo=1)][16 rows * 80B]
    __shared__ __align__(16) char sAbuf[8][4][1280];
    __shared__ float s_sum[64];

    const int tid = threadIdx.x, wid = tid >> 5, lane = tid & 31;
    if (tid < 64) s_sum[tid] = 0.f;
    __syncthreads();

    const int rowbase = (blockIdx.x * 8 + wid) * 16;
    const u32 warpBase = smem_to_u32(&sAbuf[wid][0][0]);

    // ldmatrix per-lane offset: matrix m = lane>>3; row=(lane&7)+((m&1)?8:0); col m>=2 ? +16B
    const u32 ldsmOff = (u32)(((lane & 7) + ((lane >> 3) & 1) * 8) * 80 + ((lane >> 4) * 16));
    // gather: 2 lanes per row
    const int grow = rowbase + (lane >> 1);
    const int half = lane & 1;
    const u32 stsOff = (u32)((lane >> 1) * 80 + half * 32);

    float acc[16];
#pragma unroll
    for (int i = 0; i < 16; i++) acc[i] = 0.f;

    int st = 0;  // executed-tap counter -> stage parity
#pragma unroll 1
    for (int k = 0; k < K; k++) {
        int idx = (grow < N) ? __ldg(&nbr[(size_t)k * N + grow]) : -1;
        unsigned bal = __ballot_sync(0xffffffffu, idx >= 0);
        if (!bal) continue;

        u32 hw[8], lw[8];
        if (idx >= 0) {
            const float4 *f4 = (const float4 *)(feat + (size_t)idx * 32) + half * 4;
#pragma unroll
            for (int q = 0; q < 4; q++) {
                float4 f = __ldg(f4 + q);
                u32 h0 = packbf(f.x, f.y);
                u32 h1 = packbf(f.z, f.w);
                hw[2 * q] = h0; hw[2 * q + 1] = h1;
                lw[2 * q]     = packbf(f.x - lof(h0), f.y - hif(h0));
                lw[2 * q + 1] = packbf(f.z - lof(h1), f.w - hif(h1));
            }
        } else {
#pragma unroll
            for (int i = 0; i < 8; i++) { hw[i] = 0u; lw[i] = 0u; }
        }

        const u32 hiB = warpBase + (u32)(st & 1) * 2560u;
        const u32 loB = hiB + 1280u;
        st++;
        sts128(hiB + stsOff,       hw[0], hw[1], hw[2], hw[3]);
        sts128(hiB + stsOff + 16u, hw[4], hw[5], hw[6], hw[7]);
        sts128(loB + stsOff,       lw[0], lw[1], lw[2], lw[3]);
        sts128(loB + stsOff + 16u, lw[4], lw[5], lw[6], lw[7]);
        __syncwarp();

        u32 ah[8], al[8];
        ldsm4(ah + 0, hiB + ldsmOff);
        ldsm4(ah + 4, hiB + ldsmOff + 32u);
        ldsm4(al + 0, loB + ldsmOff);
        ldsm4(al + 4, loB + ldsmOff + 32u);

        // weights: hi at tap*128, lo at K*128 + tap*128 (uint4 units)
        const uint4 *wh = Wf + (size_t)k * 128 + lane * 2;
        const uint4 *wl = Wf + (size_t)K * 128 + (size_t)k * 128 + lane * 2;
        uint4 h0 = __ldg(wh);        // kc0: nc0,nc1
        uint4 h0b = __ldg(wh + 1);   // kc0: nc2,nc3
        uint4 h1 = __ldg(wh + 64);   // kc1: nc0,nc1
        uint4 h1b = __ldg(wh + 65);
        uint4 l0 = __ldg(wl);
        uint4 l0b = __ldg(wl + 1);
        uint4 l1 = __ldg(wl + 64);
        uint4 l1b = __ldg(wl + 65);

        // kc0
        mma16816(acc + 0,  ah,     h0.x,  h0.y);
        mma16816(acc + 0,  al,     h0.x,  h0.y);
        mma16816(acc + 0,  ah,     l0.x,  l0.y);
        mma16816(acc + 4,  ah,     h0.z,  h0.w);
        mma16816(acc + 4,  al,     h0.z,  h0.w);
        mma16816(acc + 4,  ah,     l0.z,  l0.w);
        mma16816(acc + 8,  ah,     h0b.x, h0b.y);
        mma16816(acc + 8,  al,     h0b.x, h0b.y);
        mma16816(acc + 8,  ah,     l0b.x, l0b.y);
        mma16816(acc + 12, ah,     h0b.z, h0b.w);
        mma16816(acc + 12, al,     h0b.z, h0b.w);
        mma16816(acc + 12, ah,     l0b.z, l0b.w);
        // kc1
        mma16816(acc + 0,  ah + 4, h1.x,  h1.y);
        mma16816(acc + 0,  al + 4, h1.x,  h1.y);
        mma16816(acc + 0,  ah + 4, l1.x,  l1.y);
        mma16816(acc + 4,  ah + 4, h1.z,  h1.w);
        mma16816(acc + 4,  al + 4, h1.z,  h1.w);
        mma16816(acc + 4,  ah + 4, l1.z,  l1.w);
        mma16816(acc + 8,  ah + 4, h1b.x, h1b.y);
        mma16816(acc + 8,  al + 4, h1b.x, h1b.y);
        mma16816(acc + 8,  ah + 4, l1b.x, l1b.y);
        mma16816(acc + 12, ah + 4, h1b.z, h1b.w);
        mma16816(acc + 12, al + 4, h1b.z, h1b.w);
        mma16816(acc + 12, ah + 4, l1b.z, l1b.w);
    }

    // ---- epilogue: store rows
    const int r1 = rowbase + (lane >> 2);
    const int r2 = r1 + 8;
    const int cb = (lane & 3) * 2;
    if (r1 < N) {
        float *o = out + (size_t)r1 * 32 + cb;
#pragma unroll
        for (int nc = 0; nc < 4; nc++)
            *(float2 *)(o + nc * 8) = make_float2(acc[nc * 4 + 0], acc[nc * 4 + 1]);
    }
    if (r2 < N) {
        float *o = out + (size_t)r2 * 32 + cb;
#pragma unroll
        for (int nc = 0; nc < 4; nc++)
            *(float2 *)(o + nc * 8) = make_float2(acc[nc * 4 + 2], acc[nc * 4 + 3]);
    }

    // ---- BN partial sums (rows >= N contribute exact zeros)
#pragma unroll
    for (int nc = 0; nc < 4; nc++) {
#pragma unroll
        for (int j = 0; j < 2; j++) {
            float a0 = acc[nc * 4 + j], a1 = acc[nc * 4 + 2 + j];
            float s = a0 + a1;
            float q = a0 * a0 + a1 * a1;
#pragma unroll
            for (int o = 16; o >= 4; o >>= 1) {
                s += __shfl_xor_sync(0xffffffffu, s, o);
                q += __shfl_xor_sync(0xffffffffu, q, o);
            }
            if (lane < 4) {
                atomicAdd(&s_sum[nc * 8 + 2 * lane + j], s);
                atomicAdd(&s_sum[32 + nc * 8 + 2 * lane + j], q);
            }
        }
    }
    __syncthreads();
    if (tid < 64) atomicAdd(&stats[tid], s_sum[tid]);
}

// ---------------------------------------------------------------------------
// Scalar FFMA2 conv for stem1 (CIN=4)
// ---------------------------------------------------------------------------
__device__ __forceinline__ void ffma2(u64 &acc, u64 a, u64 b) {
    asm volatile("fma.rn.f32x2 %0, %1, %2, %0;" : "+l"(acc) : "l"(a), "l"(b));
}
__device__ __forceinline__ u64 pack2(float x) {
    u64 r;
    asm("mov.b64 %0, {%1, %1};" : "=l"(r) : "r"(__float_as_uint(x)));
    return r;
}
__device__ __forceinline__ void ci_step(u64 *acc, const ulonglong2 *w, float fv) {
    u64 ff = pack2(fv);
#pragma unroll
    for (int j = 0; j < 8; j++) {
        ulonglong2 ww = w[j];
        ffma2(acc[2 * j],     ff, ww.x);
        ffma2(acc[2 * j + 1], ff, ww.y);
    }
}

template <int K, int CI>
__global__ void __launch_bounds__(256, 2) conv_bn_kernel(
    const float *__restrict__ feat, const int *__restrict__ nbr,
    const float *__restrict__ W, float *__restrict__ out,
    float *__restrict__ stats, int N)
{
    extern __shared__ float smemW[];
    __shared__ float s_sum[64];
    int tid = threadIdx.x;
#pragma unroll 1
    for (int i = tid; i < K * CI * 8; i += 256)
        ((float4 *)smemW)[i] = ((const float4 *)W)[i];
    if (tid < 64) s_sum[tid] = 0.f;
    __syncthreads();

    int r = blockIdx.x * 256 + tid;
    u64 acc[16];
#pragma unroll
    for (int i = 0; i < 16; i++) acc[i] = 0ULL;

    if (r < N) {
        int idx = __ldg(&nbr[r]);
#pragma unroll 1
        for (int k = 0; k < K; k++) {
            int nidx = (k + 1 < K) ? __ldg(&nbr[(size_t)(k + 1) * N + r]) : -1;
            if (idx >= 0) {
                const float4 *f4 = (const float4 *)(feat + (size_t)idx * CI);
                float4 fr[CI / 4];
#pragma unroll
                for (int j = 0; j < CI / 4; j++) fr[j] = __ldg(f4 + j);
                const ulonglong2 *wk = (const ulonglong2 *)(smemW + k * CI * 32);
#pragma unroll
                for (int j4 = 0; j4 < CI / 4; j4++) {
                    float4 f = fr[j4];
                    ci_step(acc, wk + (4 * j4 + 0) * 8, f.x);
                    ci_step(acc, wk + (4 * j4 + 1) * 8, f.y);
                    ci_step(acc, wk + (4 * j4 + 2) * 8, f.z);
                    ci_step(acc, wk + (4 * j4 + 3) * 8, f.w);
                }
            }
            idx = nidx;
        }
        float4 *o = (float4 *)(out + (size_t)r * 32);
#pragma unroll
        for (int j = 0; j < 8; j++) {
            float2 a = *(float2 *)&acc[2 * j];
            float2 b = *(float2 *)&acc[2 * j + 1];
            o[j] = make_float4(a.x, a.y, b.x, b.y);
        }
    }
#pragma unroll
    for (int c = 0; c < 32; c++) {
        float2 p = *(float2 *)&acc[c >> 1];
        float s = (c & 1) ? p.y : p.x;
        float q = s * s;
#pragma unroll
        for (int o = 16; o > 0; o >>= 1) {
            s += __shfl_xor_sync(0xffffffffu, s, o);
            q += __shfl_xor_sync(0xffffffffu, q, o);
        }
        if ((tid & 31) == 0) {
            atomicAdd(&s_sum[c], s);
            atomicAdd(&s_sum[32 + c], q);
        }
    }
    __syncthreads();
    if (tid < 64) atomicAdd(&stats[tid], s_sum[tid]);
}

// ---------------------------------------------------------------------------
// BN finalize / apply / zero
// ---------------------------------------------------------------------------
__global__ void finalize_kernel(const float *__restrict__ stats,
                                const float *__restrict__ gamma,
                                const float *__restrict__ beta,
                                float *__restrict__ ss, float invN)
{
    int c = threadIdx.x;
    float mu  = stats[c] * invN;
    float var = stats[32 + c] * invN - mu * mu;
    float s = rsqrtf(var + 1e-5f) * gamma[c];
    ss[c] = s;
    ss[32 + c] = beta[c] - mu * s;
}

__global__ void apply_kernel(const float *__restrict__ x,
                             const float *__restrict__ ss,
                             const float *__restrict__ res,
                             float *__restrict__ out, int n4)
{
    int i = blockIdx.x * blockDim.x + threadIdx.x;
    if (i >= n4) return;
    int j = i & 7;
    float4 v  = ((const float4 *)x)[i];
    float4 sc = ((const float4 *)ss)[j];
    float4 sh = ((const float4 *)ss)[8 + j];
    float4 o;
    o.x = fmaf(v.x, sc.x, sh.x);
    o.y = fmaf(v.y, sc.y, sh.y);
    o.z = fmaf(v.z, sc.z, sh.z);
    o.w = fmaf(v.w, sc.w, sh.w);
    if (res) {
        float4 rr = ((const float4 *)res)[i];
        o.x += rr.x; o.y += rr.y; o.z += rr.z; o.w += rr.w;
    }
    o.x = fmaxf(o.x, 0.f);
    o.y = fmaxf(o.y, 0.f);
    o.z = fmaxf(o.z, 0.f);
    o.w = fmaxf(o.w, 0.f);
    ((float4 *)out)[i] = o;
}

__global__ void zero_kernel(float *p, int n)
{
    int i = blockIdx.x * blockDim.x + threadIdx.x;
    if (i < n) p[i] = 0.f;
}

// ---------------------------------------------------------------------------
extern "C" void kernel_launch(void *const *d_in, const int *in_sizes, int n_in,
                              void *d_out, int out_size)
{
    const float *vf     = (const float *)d_in[0];
    const float *Wstem1 = (const float *)d_in[1];
    const float *Wstem2 = (const float *)d_in[2];
    const float *Wdown  = (const float *)d_in[3];
    const float *Wr1a   = (const float *)d_in[4];
    const float *Wr1b   = (const float *)d_in[5];
    const float *Wr2a   = (const float *)d_in[6];
    const float *Wr2b   = (const float *)d_in[7];
    const float *gammas = (const float *)d_in[8];
    const float *betas  = (const float *)d_in[9];
    const int *nbr0  = (const int *)d_in[10];
    const int *down1 = (const int *)d_in[11];
    const int *nbr1  = (const int *)d_in[12];

    int N0 = in_sizes[10] / 27;
    int N1 = in_sizes[11] / 8;

    float *bufA, *bufB, *bufC, *bufD, *stats, *ss;
    u32 *Bw;
    cudaGetSymbolAddress((void **)&bufA, g_bufA);
    cudaGetSymbolAddress((void **)&bufB, g_bufB);
    cudaGetSymbolAddress((void **)&bufC, g_bufC);
    cudaGetSymbolAddress((void **)&bufD, g_bufD);
    cudaGetSymbolAddress((void **)&stats, g_stats);
    cudaGetSymbolAddress((void **)&ss, g_ss);
    cudaGetSymbolAddress((void **)&Bw, g_Bw);

    // per-layer weight blocks (u32 units): 27-tap layer = 27*1024, down = 8*1024
    const size_t L27 = (size_t)27 * 1024;
    u32 *B_stem2 = Bw + 0 * L27;
    u32 *B_r1a   = Bw + 1 * L27;
    u32 *B_r1b   = Bw + 2 * L27;
    u32 *B_r2a   = Bw + 3 * L27;
    u32 *B_r2b   = Bw + 4 * L27;
    u32 *B_down  = Bw + 5 * L27;

    size_t sm27_4 = (size_t)27 * 4 * 32 * sizeof(float);

    int g0  = (N0 + 127) / 128;
    int g1  = (N1 + 127) / 128;
    int gs  = (N0 + 255) / 256;
    int a0n = (N0 * 8 + 255) / 256;
    int a1n = (N1 * 8 + 255) / 256;
    float invN0 = 1.f / (float)N0;
    float invN1 = 1.f / (float)N1;
    float *out = (float *)d_out;

    // weight prep: fragment-ordered split-bf16
    prep_weights<<<54, 256>>>(Wstem2, B_stem2, 27);
    prep_weights<<<54, 256>>>(Wr1a,   B_r1a,   27);
    prep_weights<<<54, 256>>>(Wr1b,   B_r1b,   27);
    prep_weights<<<54, 256>>>(Wr2a,   B_r2a,   27);
    prep_weights<<<54, 256>>>(Wr2b,   B_r2b,   27);
    prep_weights<<<16, 256>>>(Wdown,  B_down,  8);

    zero_kernel<<<1, 448>>>(stats, 448);

    // stem1 (CIN=4): scalar path
    conv_bn_kernel<27, 4><<<gs, 256, sm27_4>>>(vf, nbr0, Wstem1, bufA, stats + 0, N0);
    finalize_kernel<<<1, 32>>>(stats + 0, gammas + 0, betas + 0, ss + 0, invN0);
    apply_kernel<<<a0n, 256>>>(bufA, ss + 0, nullptr, bufB, N0 * 8);

    // stem2 (HMMA)
    mma_conv_kernel<27><<<g0, 256>>>(bufB, nbr0, (const uint4 *)B_stem2, bufA, stats + 64, N0);
    finalize_kernel<<<1, 32>>>(stats + 64, gammas + 32, betas + 32, ss + 64, invN0);
    apply_kernel<<<a0n, 256>>>(bufA, ss + 64, nullptr, bufB, N0 * 8);

    // down (K=8)
    mma_conv_kernel<8><<<g1, 256>>>(bufB, down1, (const uint4 *)B_down, bufC, stats + 128, N1);
    finalize_kernel<<<1, 32>>>(stats + 128, gammas + 64, betas + 64, ss + 128, invN1);
    apply_kernel<<<a1n, 256>>>(bufC, ss + 128, nullptr, bufD, N1 * 8);   // bufD = x1

    // res block 1
    mma_conv_kernel<27><<<g1, 256>>>(bufD, nbr1, (const uint4 *)B_r1a, bufC, stats + 192, N1);
    finalize_kernel<<<1, 32>>>(stats + 192, gammas + 96, betas + 96, ss + 192, invN1);
    apply_kernel<<<a1n, 256>>>(bufC, ss + 192, nullptr, bufA, N1 * 8);

    mma_conv_kernel<27><<<g1, 256>>>(bufA, nbr1, (const uint4 *)B_r1b, bufC, stats + 256, N1);
    finalize_kernel<<<1, 32>>>(stats + 256, gammas + 128, betas + 128, ss + 256, invN1);
    apply_kernel<<<a1n, 256>>>(bufC, ss + 256, bufD, bufB, N1 * 8);      // bufB = x1'

    // res block 2
    mma_conv_kernel<27><<<g1, 256>>>(bufB, nbr1, (const uint4 *)B_r2a, bufC, stats + 320, N1);
    finalize_kernel<<<1, 32>>>(stats + 320, gammas + 160, betas + 160, ss + 320, invN1);
    apply_kernel<<<a1n, 256>>>(bufC, ss + 320, nullptr, bufA, N1 * 8);

    mma_conv_kernel<27><<<g1, 256>>>(bufA, nbr1, (const uint4 *)B_r2b, bufC, stats + 384, N1);
    finalize_kernel<<<1, 32>>>(stats + 384, gammas + 192, betas + 192, ss + 384, invN1);
    apply_kernel<<<a1n, 256>>>(bufC, ss + 384, bufB, out, N1 * 8);       // final output
}

// round 4
// speedup vs baseline: 2.5071x; 1.3683x over previous
#include <cuda_runtime.h>
#include <cuda_bf16.h>
#include <cstdint>

typedef unsigned long long u64;
typedef unsigned int u32;

// ---------------------------------------------------------------------------
// Scratch (no allocations allowed)
// ---------------------------------------------------------------------------
#define MAXN 450000
__device__ float g_bufA[(size_t)MAXN * 32];
__device__ float g_bufB[(size_t)MAXN * 32];
__device__ float g_bufC[(size_t)MAXN * 32];
__device__ float g_bufD[(size_t)MAXN * 32];
__device__ float g_stats[7 * 64];   // per layer: sum[32], sumsq[32]
__device__ float g_ss[7 * 64];      // per layer: scale[32], shift[32]
// Fragment-ordered split-bf16 weights:
// per layer: hi[K*512 u32] then lo[K*512 u32]. 5 layers K=27 + 1 layer K=8.
__device__ u32 g_Bw[5 * 27 * 1024 + 8 * 1024];

// ---------------------------------------------------------------------------
// helpers
// ---------------------------------------------------------------------------
// pack: low half <- a, high half <- b
__device__ __forceinline__ u32 packbf(float a, float b) {
    u32 r;
    asm("cvt.rn.bf16x2.f32 %0, %1, %2;" : "=r"(r) : "f"(b), "f"(a));
    return r;
}
__device__ __forceinline__ float lof(u32 h) { return __uint_as_float(h << 16); }
__device__ __forceinline__ float hif(u32 h) { return __uint_as_float(h & 0xFFFF0000u); }

__device__ __forceinline__ void mma16816(float *d, const u32 *a, u32 b0, u32 b1) {
    asm volatile(
        "mma.sync.aligned.m16n8k16.row.col.f32.bf16.bf16.f32 "
        "{%0,%1,%2,%3}, {%4,%5,%6,%7}, {%8,%9}, {%0,%1,%2,%3};"
        : "+f"(d[0]), "+f"(d[1]), "+f"(d[2]), "+f"(d[3])
        : "r"(a[0]), "r"(a[1]), "r"(a[2]), "r"(a[3]), "r"(b0), "r"(b1));
}

// split one float2 into hi/lo bf16x2
__device__ __forceinline__ void cvt2(float2 f, u32 &h, u32 &l) {
    h = packbf(f.x, f.y);
    l = packbf(f.x - lof(h), f.y - hif(h));
}

// gather 8 float2 for the two fragment rows of this lane (predicated)
__device__ __forceinline__ void loadf(float2 *f, const float *__restrict__ feat,
                                      int i0, int i1, int cb) {
    if (i0 >= 0) {
        const float2 *p = (const float2 *)(feat + (size_t)i0 * 32 + cb);
        f[0] = __ldg(p); f[1] = __ldg(p + 4); f[2] = __ldg(p + 8); f[3] = __ldg(p + 12);
    } else {
        f[0] = f[1] = f[2] = f[3] = make_float2(0.f, 0.f);
    }
    if (i1 >= 0) {
        const float2 *p = (const float2 *)(feat + (size_t)i1 * 32 + cb);
        f[4] = __ldg(p); f[5] = __ldg(p + 4); f[6] = __ldg(p + 8); f[7] = __ldg(p + 12);
    } else {
        f[4] = f[5] = f[6] = f[7] = make_float2(0.f, 0.f);
    }
}

// ---------------------------------------------------------------------------
// Weight prep: W[k][ci][co] fp32 -> per-thread fragment order.
// For mma m16n8k16 col-major B: thread t holds
//   b0 = (k=kc*16+2c+0/1, n=nc*8+t/4), b1 = (k=kc*16+2c+8+0/1, n)
// hi layout: [tap][kc][lane][nc][j]  (512 u32/tap); lo at +K*512.
// ---------------------------------------------------------------------------
__global__ void prep_weights(const float *__restrict__ W, u32 *__restrict__ out, int K)
{
    int t = blockIdx.x * 256 + threadIdx.x;
    if (t >= K * 512) return;
    int r    = t & 511;
    int tap  = t >> 9;
    int kc   = r >> 8;
    int r2   = r & 255;
    int lane = r2 >> 3;
    int nc   = (r2 >> 1) & 3;
    int j    = r2 & 1;
    int k0   = kc * 16 + (lane & 3) * 2 + j * 8;
    int n    = nc * 8 + (lane >> 2);
    float w0 = W[((size_t)tap * 32 + k0) * 32 + n];
    float w1 = W[((size_t)tap * 32 + k0 + 1) * 32 + n];
    u32 h = packbf(w0, w1);
    u32 l = packbf(w0 - lof(h), w1 - hif(h));
    out[t] = h;
    out[(size_t)K * 512 + t] = l;
}

// ---------------------------------------------------------------------------
// HMMA gather-spconv + BN partial sums. Register-direct fragments, no smem.
// 128 rows / CTA (16 per warp), 256 threads. 2-deep software pipeline.
// ---------------------------------------------------------------------------
template <int K>
__global__ void __launch_bounds__(256, 2) mma_conv_kernel(
    const float *__restrict__ feat,   // [*, 32]
    const int   *__restrict__ nbr,    // [K, N]
    const uint4 *__restrict__ Wf,     // fragment-ordered weights (hi then lo)
    float       *__restrict__ out,    // [N, 32] raw pre-BN
    float       *__restrict__ stats,  // [64]
    int N)
{
    __shared__ float s_sum[64];

    const int tid = threadIdx.x, wid = tid >> 5, lane = tid & 31;
    if (tid < 64) s_sum[tid] = 0.f;
    __syncthreads();

    const int rowbase = (blockIdx.x * 8 + wid) * 16;
    const int r_lo = rowbase + (lane >> 2);
    const int r_hi = r_lo + 8;
    const int cb = (lane & 3) * 2;
    const bool v_lo = (r_lo < N), v_hi = (r_hi < N);

    float acc[16];
#pragma unroll
    for (int i = 0; i < 16; i++) acc[i] = 0.f;

    // pipeline state: indices for k (cur) and k+1 (next); features for k
    int i0c = v_lo ? __ldg(nbr + r_lo) : -1;
    int i1c = v_hi ? __ldg(nbr + r_hi) : -1;
    int i0n = -1, i1n = -1;
    if (K > 1) {
        i0n = v_lo ? __ldg(nbr + N + r_lo) : -1;
        i1n = v_hi ? __ldg(nbr + N + r_hi) : -1;
    }
    float2 fc[8], fn[8];
    loadf(fc, feat, i0c, i1c, cb);

#pragma unroll 2
    for (int k = 0; k < K; k++) {
        // prefetch idx for k+2
        int i0n2 = -1, i1n2 = -1;
        if (k + 2 < K) {
            i0n2 = v_lo ? __ldg(nbr + (size_t)(k + 2) * N + r_lo) : -1;
            i1n2 = v_hi ? __ldg(nbr + (size_t)(k + 2) * N + r_hi) : -1;
        }
        // prefetch features for k+1 (idx loaded one iteration ago)
        loadf(fn, feat, i0n, i1n, cb);

        unsigned bal = __ballot_sync(0xffffffffu, (i0c >= 0) || (i1c >= 0));
        if (bal) {
            // fragments: ah[0..3] kc0 {a0,a1,a2,a3}, ah[4..7] kc1
            u32 ah[8], al[8];
            cvt2(fc[0], ah[0], al[0]); cvt2(fc[4], ah[1], al[1]);
            cvt2(fc[1], ah[2], al[2]); cvt2(fc[5], ah[3], al[3]);
            cvt2(fc[2], ah[4], al[4]); cvt2(fc[6], ah[5], al[5]);
            cvt2(fc[3], ah[6], al[6]); cvt2(fc[7], ah[7], al[7]);

            const uint4 *wh = Wf + (size_t)k * 128 + lane * 2;
            const uint4 *wl = wh + (size_t)K * 128;
            uint4 h0  = __ldg(wh);        // kc0: nc0,nc1
            uint4 h0b = __ldg(wh + 1);    // kc0: nc2,nc3
            uint4 h1  = __ldg(wh + 64);   // kc1: nc0,nc1
            uint4 h1b = __ldg(wh + 65);
            uint4 l0  = __ldg(wl);
            uint4 l0b = __ldg(wl + 1);
            uint4 l1  = __ldg(wl + 64);
            uint4 l1b = __ldg(wl + 65);

            // kc0
            mma16816(acc + 0,  ah,     h0.x,  h0.y);
            mma16816(acc + 0,  al,     h0.x,  h0.y);
            mma16816(acc + 0,  ah,     l0.x,  l0.y);
            mma16816(acc + 4,  ah,     h0.z,  h0.w);
            mma16816(acc + 4,  al,     h0.z,  h0.w);
            mma16816(acc + 4,  ah,     l0.z,  l0.w);
            mma16816(acc + 8,  ah,     h0b.x, h0b.y);
            mma16816(acc + 8,  al,     h0b.x, h0b.y);
            mma16816(acc + 8,  ah,     l0b.x, l0b.y);
            mma16816(acc + 12, ah,     h0b.z, h0b.w);
            mma16816(acc + 12, al,     h0b.z, h0b.w);
            mma16816(acc + 12, ah,     l0b.z, l0b.w);
            // kc1
            mma16816(acc + 0,  ah + 4, h1.x,  h1.y);
            mma16816(acc + 0,  al + 4, h1.x,  h1.y);
            mma16816(acc + 0,  ah + 4, l1.x,  l1.y);
            mma16816(acc + 4,  ah + 4, h1.z,  h1.w);
            mma16816(acc + 4,  al + 4, h1.z,  h1.w);
            mma16816(acc + 4,  ah + 4, l1.z,  l1.w);
            mma16816(acc + 8,  ah + 4, h1b.x, h1b.y);
            mma16816(acc + 8,  al + 4, h1b.x, h1b.y);
            mma16816(acc + 8,  ah + 4, l1b.x, l1b.y);
            mma16816(acc + 12, ah + 4, h1b.z, h1b.w);
            mma16816(acc + 12, al + 4, h1b.z, h1b.w);
            mma16816(acc + 12, ah + 4, l1b.z, l1b.w);
        }
        // shift pipeline
        i0c = i0n; i1c = i1n; i0n = i0n2; i1n = i1n2;
#pragma unroll
        for (int q = 0; q < 8; q++) fc[q] = fn[q];
    }

    // ---- epilogue: store rows (C fragment: rows r_lo/r_hi, cols nc*8+cb+{0,1})
    if (v_lo) {
        float *o = out + (size_t)r_lo * 32 + cb;
#pragma unroll
        for (int nc = 0; nc < 4; nc++)
            *(float2 *)(o + nc * 8) = make_float2(acc[nc * 4 + 0], acc[nc * 4 + 1]);
    }
    if (v_hi) {
        float *o = out + (size_t)r_hi * 32 + cb;
#pragma unroll
        for (int nc = 0; nc < 4; nc++)
            *(float2 *)(o + nc * 8) = make_float2(acc[nc * 4 + 2], acc[nc * 4 + 3]);
    }

    // ---- BN partial sums (rows >= N hold exact zeros)
#pragma unroll
    for (int nc = 0; nc < 4; nc++) {
#pragma unroll
        for (int j = 0; j < 2; j++) {
            float a0 = acc[nc * 4 + j], a1 = acc[nc * 4 + 2 + j];
            float s = a0 + a1;
            float q = a0 * a0 + a1 * a1;
#pragma unroll
            for (int o = 16; o >= 4; o >>= 1) {
                s += __shfl_xor_sync(0xffffffffu, s, o);
                q += __shfl_xor_sync(0xffffffffu, q, o);
            }
            if (lane < 4) {
                atomicAdd(&s_sum[nc * 8 + 2 * lane + j], s);
                atomicAdd(&s_sum[32 + nc * 8 + 2 * lane + j], q);
            }
        }
    }
    __syncthreads();
    if (tid < 64) atomicAdd(&stats[tid], s_sum[tid]);
}

// ---------------------------------------------------------------------------
// Scalar FFMA2 conv for stem1 (CIN=4)
// ---------------------------------------------------------------------------
__device__ __forceinline__ void ffma2(u64 &acc, u64 a, u64 b) {
    asm volatile("fma.rn.f32x2 %0, %1, %2, %0;" : "+l"(acc) : "l"(a), "l"(b));
}
__device__ __forceinline__ u64 pack2(float x) {
    u64 r;
    asm("mov.b64 %0, {%1, %1};" : "=l"(r) : "r"(__float_as_uint(x)));
    return r;
}
__device__ __forceinline__ void ci_step(u64 *acc, const ulonglong2 *w, float fv) {
    u64 ff = pack2(fv);
#pragma unroll
    for (int j = 0; j < 8; j++) {
        ulonglong2 ww = w[j];
        ffma2(acc[2 * j],     ff, ww.x);
        ffma2(acc[2 * j + 1], ff, ww.y);
    }
}

template <int K, int CI>
__global__ void __launch_bounds__(256, 2) conv_bn_kernel(
    const float *__restrict__ feat, const int *__restrict__ nbr,
    const float *__restrict__ W, float *__restrict__ out,
    float *__restrict__ stats, int N)
{
    extern __shared__ float smemW[];
    __shared__ float s_sum[64];
    int tid = threadIdx.x;
#pragma unroll 1
    for (int i = tid; i < K * CI * 8; i += 256)
        ((float4 *)smemW)[i] = ((const float4 *)W)[i];
    if (tid < 64) s_sum[tid] = 0.f;
    __syncthreads();

    int r = blockIdx.x * 256 + tid;
    u64 acc[16];
#pragma unroll
    for (int i = 0; i < 16; i++) acc[i] = 0ULL;

    if (r < N) {
        int idx = __ldg(&nbr[r]);
#pragma unroll 1
        for (int k = 0; k < K; k++) {
            int nidx = (k + 1 < K) ? __ldg(&nbr[(size_t)(k + 1) * N + r]) : -1;
            if (idx >= 0) {
                const float4 *f4 = (const float4 *)(feat + (size_t)idx * CI);
                float4 fr[CI / 4];
#pragma unroll
                for (int j = 0; j < CI / 4; j++) fr[j] = __ldg(f4 + j);
                const ulonglong2 *wk = (const ulonglong2 *)(smemW + k * CI * 32);
#pragma unroll
                for (int j4 = 0; j4 < CI / 4; j4++) {
                    float4 f = fr[j4];
                    ci_step(acc, wk + (4 * j4 + 0) * 8, f.x);
                    ci_step(acc, wk + (4 * j4 + 1) * 8, f.y);
                    ci_step(acc, wk + (4 * j4 + 2) * 8, f.z);
                    ci_step(acc, wk + (4 * j4 + 3) * 8, f.w);
                }
            }
            idx = nidx;
        }
        float4 *o = (float4 *)(out + (size_t)r * 32);
#pragma unroll
        for (int j = 0; j < 8; j++) {
            float2 a = *(float2 *)&acc[2 * j];
            float2 b = *(float2 *)&acc[2 * j + 1];
            o[j] = make_float4(a.x, a.y, b.x, b.y);
        }
    }
#pragma unroll
    for (int c = 0; c < 32; c++) {
        float2 p = *(float2 *)&acc[c >> 1];
        float s = (c & 1) ? p.y : p.x;
        float q = s * s;
#pragma unroll
        for (int o = 16; o > 0; o >>= 1) {
            s += __shfl_xor_sync(0xffffffffu, s, o);
            q += __shfl_xor_sync(0xffffffffu, q, o);
        }
        if ((tid & 31) == 0) {
            atomicAdd(&s_sum[c], s);
            atomicAdd(&s_sum[32 + c], q);
        }
    }
    __syncthreads();
    if (tid < 64) atomicAdd(&stats[tid], s_sum[tid]);
}

// ---------------------------------------------------------------------------
// BN finalize / apply / zero
// ---------------------------------------------------------------------------
__global__ void finalize_kernel(const float *__restrict__ stats,
                                const float *__restrict__ gamma,
                                const float *__restrict__ beta,
                                float *__restrict__ ss, float invN)
{
    int c = threadIdx.x;
    float mu  = stats[c] * invN;
    float var = stats[32 + c] * invN - mu * mu;
    float s = rsqrtf(var + 1e-5f) * gamma[c];
    ss[c] = s;
    ss[32 + c] = beta[c] - mu * s;
}

__global__ void apply_kernel(const float *__restrict__ x,
                             const float *__restrict__ ss,
                             const float *__restrict__ res,
                             float *__restrict__ out, int n4)
{
    int i = blockIdx.x * blockDim.x + threadIdx.x;
    if (i >= n4) return;
    int j = i & 7;
    float4 v  = ((const float4 *)x)[i];
    float4 sc = ((const float4 *)ss)[j];
    float4 sh = ((const float4 *)ss)[8 + j];
    float4 o;
    o.x = fmaf(v.x, sc.x, sh.x);
    o.y = fmaf(v.y, sc.y, sh.y);
    o.z = fmaf(v.z, sc.z, sh.z);
    o.w = fmaf(v.w, sc.w, sh.w);
    if (res) {
        float4 rr = ((const float4 *)res)[i];
        o.x += rr.x; o.y += rr.y; o.z += rr.z; o.w += rr.w;
    }
    o.x = fmaxf(o.x, 0.f);
    o.y = fmaxf(o.y, 0.f);
    o.z = fmaxf(o.z, 0.f);
    o.w = fmaxf(o.w, 0.f);
    ((float4 *)out)[i] = o;
}

__global__ void zero_kernel(float *p, int n)
{
    int i = blockIdx.x * blockDim.x + threadIdx.x;
    if (i < n) p[i] = 0.f;
}

// ---------------------------------------------------------------------------
extern "C" void kernel_launch(void *const *d_in, const int *in_sizes, int n_in,
                              void *d_out, int out_size)
{
    const float *vf     = (const float *)d_in[0];
    const float *Wstem1 = (const float *)d_in[1];
    const float *Wstem2 = (const float *)d_in[2];
    const float *Wdown  = (const float *)d_in[3];
    const float *Wr1a   = (const float *)d_in[4];
    const float *Wr1b   = (const float *)d_in[5];
    const float *Wr2a   = (const float *)d_in[6];
    const float *Wr2b   = (const float *)d_in[7];
    const float *gammas = (const float *)d_in[8];
    const float *betas  = (const float *)d_in[9];
    const int *nbr0  = (const int *)d_in[10];
    const int *down1 = (const int *)d_in[11];
    const int *nbr1  = (const int *)d_in[12];

    int N0 = in_sizes[10] / 27;
    int N1 = in_sizes[11] / 8;

    float *bufA, *bufB, *bufC, *bufD, *stats, *ss;
    u32 *Bw;
    cudaGetSymbolAddress((void **)&bufA, g_bufA);
    cudaGetSymbolAddress((void **)&bufB, g_bufB);
    cudaGetSymbolAddress((void **)&bufC, g_bufC);
    cudaGetSymbolAddress((void **)&bufD, g_bufD);
    cudaGetSymbolAddress((void **)&stats, g_stats);
    cudaGetSymbolAddress((void **)&ss, g_ss);
    cudaGetSymbolAddress((void **)&Bw, g_Bw);

    const size_t L27 = (size_t)27 * 1024;
    u32 *B_stem2 = Bw + 0 * L27;
    u32 *B_r1a   = Bw + 1 * L27;
    u32 *B_r1b   = Bw + 2 * L27;
    u32 *B_r2a   = Bw + 3 * L27;
    u32 *B_r2b   = Bw + 4 * L27;
    u32 *B_down  = Bw + 5 * L27;

    size_t sm27_4 = (size_t)27 * 4 * 32 * sizeof(float);

    int g0  = (N0 + 127) / 128;
    int g1  = (N1 + 127) / 128;
    int gs  = (N0 + 255) / 256;
    int a0n = (N0 * 8 + 255) / 256;
    int a1n = (N1 * 8 + 255) / 256;
    float invN0 = 1.f / (float)N0;
    float invN1 = 1.f / (float)N1;
    float *out = (float *)d_out;

    prep_weights<<<54, 256>>>(Wstem2, B_stem2, 27);
    prep_weights<<<54, 256>>>(Wr1a,   B_r1a,   27);
    prep_weights<<<54, 256>>>(Wr1b,   B_r1b,   27);
    prep_weights<<<54, 256>>>(Wr2a,   B_r2a,   27);
    prep_weights<<<54, 256>>>(Wr2b,   B_r2b,   27);
    prep_weights<<<16, 256>>>(Wdown,  B_down,  8);

    zero_kernel<<<1, 448>>>(stats, 448);

    // stem1 (CIN=4): scalar path
    conv_bn_kernel<27, 4><<<gs, 256, sm27_4>>>(vf, nbr0, Wstem1, bufA, stats + 0, N0);
    finalize_kernel<<<1, 32>>>(stats + 0, gammas + 0, betas + 0, ss + 0, invN0);
    apply_kernel<<<a0n, 256>>>(bufA, ss + 0, nullptr, bufB, N0 * 8);

    // stem2 (HMMA)
    mma_conv_kernel<27><<<g0, 256>>>(bufB, nbr0, (const uint4 *)B_stem2, bufA, stats + 64, N0);
    finalize_kernel<<<1, 32>>>(stats + 64, gammas + 32, betas + 32, ss + 64, invN0);
    apply_kernel<<<a0n, 256>>>(bufA, ss + 64, nullptr, bufB, N0 * 8);

    // down (K=8)
    mma_conv_kernel<8><<<g1, 256>>>(bufB, down1, (const uint4 *)B_down, bufC, stats + 128, N1);
    finalize_kernel<<<1, 32>>>(stats + 128, gammas + 64, betas + 64, ss + 128, invN1);
    apply_kernel<<<a1n, 256>>>(bufC, ss + 128, nullptr, bufD, N1 * 8);   // bufD = x1

    // res block 1
    mma_conv_kernel<27><<<g1, 256>>>(bufD, nbr1, (const uint4 *)B_r1a, bufC, stats + 192, N1);
    finalize_kernel<<<1, 32>>>(stats + 192, gammas + 96, betas + 96, ss + 192, invN1);
    apply_kernel<<<a1n, 256>>>(bufC, ss + 192, nullptr, bufA, N1 * 8);

    mma_conv_kernel<27><<<g1, 256>>>(bufA, nbr1, (const uint4 *)B_r1b, bufC, stats + 256, N1);
    finalize_kernel<<<1, 32>>>(stats + 256, gammas + 128, betas + 128, ss + 256, invN1);
    apply_kernel<<<a1n, 256>>>(bufC, ss + 256, bufD, bufB, N1 * 8);      // bufB = x1'

    // res block 2
    mma_conv_kernel<27><<<g1, 256>>>(bufB, nbr1, (const uint4 *)B_r2a, bufC, stats + 320, N1);
    finalize_kernel<<<1, 32>>>(stats + 320, gammas + 160, betas + 160, ss + 320, invN1);
    apply_kernel<<<a1n, 256>>>(bufC, ss + 320, nullptr, bufA, N1 * 8);

    mma_conv_kernel<27><<<g1, 256>>>(bufA, nbr1, (const uint4 *)B_r2b, bufC, stats + 384, N1);
    finalize_kernel<<<1, 32>>>(stats + 384, gammas + 192, betas + 192, ss + 384, invN1);
    apply_kernel<<<a1n, 256>>>(bufC, ss + 384, bufB, out, N1 * 8);       // final output
}

// round 5
// speedup vs baseline: 3.4643x; 1.3818x over previous
#include <cuda_runtime.h>
#include <cuda_bf16.h>
#include <cstdint>

typedef unsigned long long u64;
typedef unsigned int u32;

// ---------------------------------------------------------------------------
// Scratch (no allocations allowed)
// ---------------------------------------------------------------------------
#define MAXN 450000
__device__ float g_bufA[(size_t)MAXN * 32];
__device__ float g_bufB[(size_t)MAXN * 32];
__device__ float g_bufC[(size_t)MAXN * 32];
__device__ float g_bufD[(size_t)MAXN * 32];
__device__ float g_stats[7 * 64];   // per layer: sum[32], sumsq[32]
__device__ float g_ss[7 * 64];      // per layer: scale[32], shift[32]
// Fragment-ordered split-bf16 weights: per layer K*1024 u32 (hi K*512 then lo)
__device__ u32 g_Bw[5 * 27 * 1024 + 8 * 1024];
__device__ u32 g_Bs1[2 * 1792];      // stem1: 7 groups * 256 u32 hi + lo

// ---------------------------------------------------------------------------
// helpers
// ---------------------------------------------------------------------------
// pack: low half <- a, high half <- b
__device__ __forceinline__ u32 packbf(float a, float b) {
    u32 r;
    asm("cvt.rn.bf16x2.f32 %0, %1, %2;" : "=r"(r) : "f"(b), "f"(a));
    return r;
}
__device__ __forceinline__ float lof(u32 h) { return __uint_as_float(h << 16); }
__device__ __forceinline__ float hif(u32 h) { return __uint_as_float(h & 0xFFFF0000u); }
__device__ __forceinline__ void cvtp(float x, float y, u32 &h, u32 &l) {
    h = packbf(x, y);
    l = packbf(x - lof(h), y - hif(h));
}
__device__ __forceinline__ void mma16816(float *d, const u32 *a, u32 b0, u32 b1) {
    asm volatile(
        "mma.sync.aligned.m16n8k16.row.col.f32.bf16.bf16.f32 "
        "{%0,%1,%2,%3}, {%4,%5,%6,%7}, {%8,%9}, {%0,%1,%2,%3};"
        : "+f"(d[0]), "+f"(d[1]), "+f"(d[2]), "+f"(d[3])
        : "r"(a[0]), "r"(a[1]), "r"(a[2]), "r"(a[3]), "r"(b0), "r"(b1));
}
// 12 MMAs: one kc pass (hh, lh, hl) over 4 nc
__device__ __forceinline__ void mma_pass(float *acc, const u32 *ah, const u32 *al,
                                         uint4 H0, uint4 H1, uint4 L0, uint4 L1) {
    mma16816(acc + 0,  ah, H0.x, H0.y);
    mma16816(acc + 0,  al, H0.x, H0.y);
    mma16816(acc + 0,  ah, L0.x, L0.y);
    mma16816(acc + 4,  ah, H0.z, H0.w);
    mma16816(acc + 4,  al, H0.z, H0.w);
    mma16816(acc + 4,  ah, L0.z, L0.w);
    mma16816(acc + 8,  ah, H1.x, H1.y);
    mma16816(acc + 8,  al, H1.x, H1.y);
    mma16816(acc + 8,  ah, L1.x, L1.y);
    mma16816(acc + 12, ah, H1.z, H1.w);
    mma16816(acc + 12, al, H1.z, H1.w);
    mma16816(acc + 12, ah, L1.z, L1.w);
}

// ---------------------------------------------------------------------------
// Weight prep (generic C32 layers): physical channel for (kc,m,h,j) = 8m+4kc+2h+j
// layout per tap: [kc][c2][lane][e] (512 u32); hi block [K*512], lo at +K*512.
// ---------------------------------------------------------------------------
__global__ void prep_weights(const float *__restrict__ W, u32 *__restrict__ out, int K)
{
    int t = blockIdx.x * 256 + threadIdx.x;
    if (t >= K * 512) return;
    int tap  = t >> 9;
    int r    = t & 511;
    int kc   = r >> 8;
    int c2   = (r >> 7) & 1;
    int lane = (r >> 2) & 31;
    int e    = r & 3;
    int nc   = c2 * 2 + (e >> 1);
    int h    = e & 1;
    int mm   = lane & 3;
    int n    = nc * 8 + (lane >> 2);
    int k0   = 8 * mm + 4 * kc + 2 * h;
    float w0 = W[((size_t)tap * 32 + k0) * 32 + n];
    float w1 = W[((size_t)tap * 32 + k0 + 1) * 32 + n];
    u32 hh = packbf(w0, w1);
    u32 ll = packbf(w0 - lof(hh), w1 - hif(hh));
    out[t] = hh;
    out[(size_t)K * 512 + t] = ll;
}

// stem1 prep: 27 taps x 4 ci packed as 7 groups of K=16 (4 taps).
// logical k in group = 2*mm + 8*h + j -> tap = 4g + (k>>2), ci = k&3.
__global__ void prep_stem1(const float *__restrict__ W, u32 *__restrict__ out)
{
    int t = blockIdx.x * 256 + threadIdx.x;
    if (t >= 1792) return;
    int g    = t >> 8;
    int r    = t & 255;
    int c2   = r >> 7;
    int lane = (r >> 2) & 31;
    int e    = r & 3;
    int nc   = c2 * 2 + (e >> 1);
    int h    = e & 1;
    int mm   = lane & 3;
    int n    = nc * 8 + (lane >> 2);
    int k0   = 2 * mm + 8 * h;
    int tap  = 4 * g + (k0 >> 2);
    int ci   = k0 & 3;
    float w0 = (tap < 27) ? W[((size_t)tap * 4 + ci) * 32 + n] : 0.f;
    float w1 = (tap < 27) ? W[((size_t)tap * 4 + ci + 1) * 32 + n] : 0.f;
    u32 hh = packbf(w0, w1);
    u32 ll = packbf(w0 - lof(hh), w1 - hif(hh));
    out[t] = hh;
    out[1792 + t] = ll;
}

// ---------------------------------------------------------------------------
// Generic HMMA gather-spconv (CI=32) + BN partial sums.
// 256 threads, 8 warps, 32 rows/warp = 256 rows/CTA. Weights in smem.
// ---------------------------------------------------------------------------
template <int K>
__global__ void __launch_bounds__(256, 2) mma_conv_kernel(
    const float *__restrict__ feat,   // [*, 32]
    const int   *__restrict__ nbr,    // [K, N]
    const uint4 *__restrict__ Wf,     // fragment weights, K*256 uint4 (hi+lo)
    float       *__restrict__ out,    // [N, 32] raw pre-BN
    float       *__restrict__ stats,  // [64]
    int N)
{
    extern __shared__ u32 sW[];       // K*1024 u32
    __shared__ float s_sum[64];
    const int tid = threadIdx.x, wid = tid >> 5, lane = tid & 31;

    {
        uint4 *dst = (uint4 *)sW;
#pragma unroll 4
        for (int i = tid; i < K * 256; i += 256) dst[i] = __ldg(Wf + i);
    }
    if (tid < 64) s_sum[tid] = 0.f;
    __syncthreads();

    const int rowbase = (blockIdx.x * 8 + wid) * 32;
    const int m = lane & 3;
    const int rq = lane >> 2;
    int r0 = rowbase + rq;
    const int coff = m * 8;            // physical channel base

    float acc[32];
#pragma unroll
    for (int i = 0; i < 32; i++) acc[i] = 0.f;

    int idxc[4], idxn[4];
#pragma unroll
    for (int q = 0; q < 4; q++) {
        int rr = r0 + q * 8;
        idxc[q] = (rr < N) ? __ldg(nbr + rr) : -1;
    }

#pragma unroll 1
    for (int k = 0; k < K; k++) {
        // prefetch next tap's indices
#pragma unroll
        for (int q = 0; q < 4; q++) {
            int rr = r0 + q * 8;
            idxn[q] = (k + 1 < K && rr < N) ? __ldg(nbr + (size_t)(k + 1) * N + rr) : -1;
        }
        int anyv = (idxc[0] >= 0) | (idxc[1] >= 0) | (idxc[2] >= 0) | (idxc[3] >= 0);
        if (__ballot_sync(0xffffffffu, anyv)) {
            // gather: 2 float4 per row
            float4 fa[4], fb[4];
#pragma unroll
            for (int q = 0; q < 4; q++) {
                if (idxc[q] >= 0) {
                    const float4 *p = (const float4 *)(feat + (size_t)idxc[q] * 32 + coff);
                    fa[q] = __ldg(p);
                    fb[q] = __ldg(p + 1);
                } else {
                    fa[q] = make_float4(0.f, 0.f, 0.f, 0.f);
                    fb[q] = make_float4(0.f, 0.f, 0.f, 0.f);
                }
            }
            // weights from smem (conflict-free LDS.128)
            const u32 hb = (u32)k * 512u;
            const u32 lb = (u32)K * 512u + (u32)k * 512u;
            uint4 H00 = ((const uint4 *)(sW + hb))[lane];          // kc0 nc01
            uint4 H01 = ((const uint4 *)(sW + hb + 128))[lane];    // kc0 nc23
            uint4 H10 = ((const uint4 *)(sW + hb + 256))[lane];    // kc1 nc01
            uint4 H11 = ((const uint4 *)(sW + hb + 384))[lane];
            uint4 L00 = ((const uint4 *)(sW + lb))[lane];
            uint4 L01 = ((const uint4 *)(sW + lb + 128))[lane];
            uint4 L10 = ((const uint4 *)(sW + lb + 256))[lane];
            uint4 L11 = ((const uint4 *)(sW + lb + 384))[lane];

#pragma unroll
            for (int b = 0; b < 2; b++) {
                // fragments for rows (2b, 2b+1)
                u32 ah0[4], al0[4], ah1[4], al1[4];
                cvtp(fa[2 * b].x,     fa[2 * b].y,     ah0[0], al0[0]);
                cvtp(fa[2 * b + 1].x, fa[2 * b + 1].y, ah0[1], al0[1]);
                cvtp(fa[2 * b].z,     fa[2 * b].w,     ah0[2], al0[2]);
                cvtp(fa[2 * b + 1].z, fa[2 * b + 1].w, ah0[3], al0[3]);
                cvtp(fb[2 * b].x,     fb[2 * b].y,     ah1[0], al1[0]);
                cvtp(fb[2 * b + 1].x, fb[2 * b + 1].y, ah1[1], al1[1]);
                cvtp(fb[2 * b].z,     fb[2 * b].w,     ah1[2], al1[2]);
                cvtp(fb[2 * b + 1].z, fb[2 * b + 1].w, ah1[3], al1[3]);
                mma_pass(acc + b * 16, ah0, al0, H00, H01, L00, L01);   // kc0
                mma_pass(acc + b * 16, ah1, al1, H10, H11, L10, L11);   // kc1
            }
        }
#pragma unroll
        for (int q = 0; q < 4; q++) idxc[q] = idxn[q];
    }

    // ---- epilogue: store rows; cols = nc*8 + m*2
#pragma unroll
    for (int b = 0; b < 2; b++) {
        int ra = rowbase + b * 16 + rq;
        int rb = ra + 8;
        if (ra < N) {
            float *o = out + (size_t)ra * 32 + m * 2;
#pragma unroll
            for (int nc = 0; nc < 4; nc++)
                *(float2 *)(o + nc * 8) = make_float2(acc[b * 16 + nc * 4], acc[b * 16 + nc * 4 + 1]);
        }
        if (rb < N) {
            float *o = out + (size_t)rb * 32 + m * 2;
#pragma unroll
            for (int nc = 0; nc < 4; nc++)
                *(float2 *)(o + nc * 8) = make_float2(acc[b * 16 + nc * 4 + 2], acc[b * 16 + nc * 4 + 3]);
        }
    }

    // ---- BN partial sums
#pragma unroll
    for (int nc = 0; nc < 4; nc++) {
#pragma unroll
        for (int j = 0; j < 2; j++) {
            float a0 = acc[nc * 4 + j], a1 = acc[nc * 4 + 2 + j];
            float a2 = acc[16 + nc * 4 + j], a3 = acc[16 + nc * 4 + 2 + j];
            float s = (a0 + a1) + (a2 + a3);
            float q = (a0 * a0 + a1 * a1) + (a2 * a2 + a3 * a3);
#pragma unroll
            for (int o = 16; o >= 4; o >>= 1) {
                s += __shfl_xor_sync(0xffffffffu, s, o);
                q += __shfl_xor_sync(0xffffffffu, q, o);
            }
            if (lane < 4) {
                atomicAdd(&s_sum[nc * 8 + 2 * lane + j], s);
                atomicAdd(&s_sum[32 + nc * 8 + 2 * lane + j], q);
            }
        }
    }
    __syncthreads();
    if (tid < 64) atomicAdd(&stats[tid], s_sum[tid]);
}

// ---------------------------------------------------------------------------
// stem1: CIN=4, 27 taps packed as 7 MMA K-groups of 4 taps.
// ---------------------------------------------------------------------------
__global__ void __launch_bounds__(256, 2) stem1_kernel(
    const float *__restrict__ feat,   // [N, 4]
    const int   *__restrict__ nbr,    // [27, N]
    const u32   *__restrict__ Wf,     // 2*1792 u32
    float       *__restrict__ out,    // [N, 32]
    float       *__restrict__ stats,
    int N)
{
    __shared__ u32 sW[3584];
    __shared__ float s_sum[64];
    const int tid = threadIdx.x, wid = tid >> 5, lane = tid & 31;

#pragma unroll 2
    for (int i = tid; i < 896; i += 256) ((uint4 *)sW)[i] = __ldg((const uint4 *)Wf + i);
    if (tid < 64) s_sum[tid] = 0.f;
    __syncthreads();

    const int rowbase = (blockIdx.x * 8 + wid) * 32;
    const int m = lane & 3;
    const int rq = lane >> 2;
    const int ci0 = (m & 1) * 2;
    const int tA0 = m >> 1;

    float acc[32];
#pragma unroll
    for (int i = 0; i < 32; i++) acc[i] = 0.f;

#pragma unroll 1
    for (int g = 0; g < 7; g++) {
        const int tA = 4 * g + tA0;
        const int tB = tA + 2;
        float2 fA[4], fB[4];
#pragma unroll
        for (int q = 0; q < 4; q++) {
            int rr = rowbase + q * 8 + rq;
            int iA = (rr < N) ? __ldg(nbr + (size_t)tA * N + rr) : -1;
            int iB = (rr < N && tB < 27) ? __ldg(nbr + (size_t)tB * N + rr) : -1;
            fA[q] = (iA >= 0) ? __ldg((const float2 *)(feat + (size_t)iA * 4 + ci0))
                              : make_float2(0.f, 0.f);
            fB[q] = (iB >= 0) ? __ldg((const float2 *)(feat + (size_t)iB * 4 + ci0))
                              : make_float2(0.f, 0.f);
        }
        uint4 H0 = ((const uint4 *)(sW + g * 256))[lane];
        uint4 H1 = ((const uint4 *)(sW + g * 256 + 128))[lane];
        uint4 L0 = ((const uint4 *)(sW + 1792 + g * 256))[lane];
        uint4 L1 = ((const uint4 *)(sW + 1792 + g * 256 + 128))[lane];
#pragma unroll
        for (int b = 0; b < 2; b++) {
            u32 ah[4], al[4];
            cvtp(fA[2 * b].x,     fA[2 * b].y,     ah[0], al[0]);
            cvtp(fA[2 * b + 1].x, fA[2 * b + 1].y, ah[1], al[1]);
            cvtp(fB[2 * b].x,     fB[2 * b].y,     ah[2], al[2]);
            cvtp(fB[2 * b + 1].x, fB[2 * b + 1].y, ah[3], al[3]);
            mma_pass(acc + b * 16, ah, al, H0, H1, L0, L1);
        }
    }

    // epilogue + BN (identical to generic)
#pragma unroll
    for (int b = 0; b < 2; b++) {
        int ra = rowbase + b * 16 + rq;
        int rb = ra + 8;
        if (ra < N) {
            float *o = out + (size_t)ra * 32 + m * 2;
#pragma unroll
            for (int nc = 0; nc < 4; nc++)
                *(float2 *)(o + nc * 8) = make_float2(acc[b * 16 + nc * 4], acc[b * 16 + nc * 4 + 1]);
        }
        if (rb < N) {
            float *o = out + (size_t)rb * 32 + m * 2;
#pragma unroll
            for (int nc = 0; nc < 4; nc++)
                *(float2 *)(o + nc * 8) = make_float2(acc[b * 16 + nc * 4 + 2], acc[b * 16 + nc * 4 + 3]);
        }
    }
#pragma unroll
    for (int nc = 0; nc < 4; nc++) {
#pragma unroll
        for (int j = 0; j < 2; j++) {
            float a0 = acc[nc * 4 + j], a1 = acc[nc * 4 + 2 + j];
            float a2 = acc[16 + nc * 4 + j], a3 = acc[16 + nc * 4 + 2 + j];
            float s = (a0 + a1) + (a2 + a3);
            float q = (a0 * a0 + a1 * a1) + (a2 * a2 + a3 * a3);
#pragma unroll
            for (int o = 16; o >= 4; o >>= 1) {
                s += __shfl_xor_sync(0xffffffffu, s, o);
                q += __shfl_xor_sync(0xffffffffu, q, o);
            }
            if (lane < 4) {
                atomicAdd(&s_sum[nc * 8 + 2 * lane + j], s);
                atomicAdd(&s_sum[32 + nc * 8 + 2 * lane + j], q);
            }
        }
    }
    __syncthreads();
    if (tid < 64) atomicAdd(&stats[tid], s_sum[tid]);
}

// ---------------------------------------------------------------------------
// BN finalize / apply / zero
// ---------------------------------------------------------------------------
__global__ void finalize_kernel(const float *__restrict__ stats,
                                const float *__restrict__ gamma,
                                const float *__restrict__ beta,
                                float *__restrict__ ss, float invN)
{
    int c = threadIdx.x;
    float mu  = stats[c] * invN;
    float var = stats[32 + c] * invN - mu * mu;
    float s = rsqrtf(var + 1e-5f) * gamma[c];
    ss[c] = s;
    ss[32 + c] = beta[c] - mu * s;
}

__global__ void apply_kernel(const float *__restrict__ x,
                             const float *__restrict__ ss,
                             const float *__restrict__ res,
                             float *__restrict__ out, int n4)
{
    int i = blockIdx.x * blockDim.x + threadIdx.x;
    if (i >= n4) return;
    int j = i & 7;
    float4 v  = ((const float4 *)x)[i];
    float4 sc = ((const float4 *)ss)[j];
    float4 sh = ((const float4 *)ss)[8 + j];
    float4 o;
    o.x = fmaf(v.x, sc.x, sh.x);
    o.y = fmaf(v.y, sc.y, sh.y);
    o.z = fmaf(v.z, sc.z, sh.z);
    o.w = fmaf(v.w, sc.w, sh.w);
    if (res) {
        float4 rr = ((const float4 *)res)[i];
        o.x += rr.x; o.y += rr.y; o.z += rr.z; o.w += rr.w;
    }
    o.x = fmaxf(o.x, 0.f);
    o.y = fmaxf(o.y, 0.f);
    o.z = fmaxf(o.z, 0.f);
    o.w = fmaxf(o.w, 0.f);
    ((float4 *)out)[i] = o;
}

__global__ void zero_kernel(float *p, int n)
{
    int i = blockIdx.x * blockDim.x + threadIdx.x;
    if (i < n) p[i] = 0.f;
}

// ---------------------------------------------------------------------------
extern "C" void kernel_launch(void *const *d_in, const int *in_sizes, int n_in,
                              void *d_out, int out_size)
{
    const float *vf     = (const float *)d_in[0];
    const float *Wstem1 = (const float *)d_in[1];
    const float *Wstem2 = (const float *)d_in[2];
    const float *Wdown  = (const float *)d_in[3];
    const float *Wr1a   = (const float *)d_in[4];
    const float *Wr1b   = (const float *)d_in[5];
    const float *Wr2a   = (const float *)d_in[6];
    const float *Wr2b   = (const float *)d_in[7];
    const float *gammas = (const float *)d_in[8];
    const float *betas  = (const float *)d_in[9];
    const int *nbr0  = (const int *)d_in[10];
    const int *down1 = (const int *)d_in[11];
    const int *nbr1  = (const int *)d_in[12];

    int N0 = in_sizes[10] / 27;
    int N1 = in_sizes[11] / 8;

    float *bufA, *bufB, *bufC, *bufD, *stats, *ss;
    u32 *Bw, *Bs1;
    cudaGetSymbolAddress((void **)&bufA, g_bufA);
    cudaGetSymbolAddress((void **)&bufB, g_bufB);
    cudaGetSymbolAddress((void **)&bufC, g_bufC);
    cudaGetSymbolAddress((void **)&bufD, g_bufD);
    cudaGetSymbolAddress((void **)&stats, g_stats);
    cudaGetSymbolAddress((void **)&ss, g_ss);
    cudaGetSymbolAddress((void **)&Bw, g_Bw);
    cudaGetSymbolAddress((void **)&Bs1, g_Bs1);

    const size_t L27 = (size_t)27 * 1024;
    u32 *B_stem2 = Bw + 0 * L27;
    u32 *B_r1a   = Bw + 1 * L27;
    u32 *B_r1b   = Bw + 2 * L27;
    u32 *B_r2a   = Bw + 3 * L27;
    u32 *B_r2b   = Bw + 4 * L27;
    u32 *B_down  = Bw + 5 * L27;

    size_t sm27 = (size_t)27 * 4096;   // 110592 B
    size_t sm8  = (size_t)8 * 4096;    // 32768 B
    cudaFuncSetAttribute(mma_conv_kernel<27>,
                         cudaFuncAttributeMaxDynamicSharedMemorySize, (int)sm27);
    cudaFuncSetAttribute(mma_conv_kernel<8>,
                         cudaFuncAttributeMaxDynamicSharedMemorySize, (int)sm8);

    int g0  = (N0 + 255) / 256;
    int g1  = (N1 + 255) / 256;
    int a0n = (N0 * 8 + 255) / 256;
    int a1n = (N1 * 8 + 255) / 256;
    float invN0 = 1.f / (float)N0;
    float invN1 = 1.f / (float)N1;
    float *out = (float *)d_out;

    prep_weights<<<54, 256>>>(Wstem2, B_stem2, 27);
    prep_weights<<<54, 256>>>(Wr1a,   B_r1a,   27);
    prep_weights<<<54, 256>>>(Wr1b,   B_r1b,   27);
    prep_weights<<<54, 256>>>(Wr2a,   B_r2a,   27);
    prep_weights<<<54, 256>>>(Wr2b,   B_r2b,   27);
    prep_weights<<<16, 256>>>(Wdown,  B_down,  8);
    prep_stem1<<<7, 256>>>(Wstem1, Bs1);

    zero_kernel<<<1, 448>>>(stats, 448);

    // stem1 (CIN=4, MMA grouped taps)
    stem1_kernel<<<g0, 256>>>(vf, nbr0, Bs1, bufA, stats + 0, N0);
    finalize_kernel<<<1, 32>>>(stats + 0, gammas + 0, betas + 0, ss + 0, invN0);
    apply_kernel<<<a0n, 256>>>(bufA, ss + 0, nullptr, bufB, N0 * 8);

    // stem2
    mma_conv_kernel<27><<<g0, 256, sm27>>>(bufB, nbr0, (const uint4 *)B_stem2, bufA, stats + 64, N0);
    finalize_kernel<<<1, 32>>>(stats + 64, gammas + 32, betas + 32, ss + 64, invN0);
    apply_kernel<<<a0n, 256>>>(bufA, ss + 64, nullptr, bufB, N0 * 8);

    // down (K=8)
    mma_conv_kernel<8><<<g1, 256, sm8>>>(bufB, down1, (const uint4 *)B_down, bufC, stats + 128, N1);
    finalize_kernel<<<1, 32>>>(stats + 128, gammas + 64, betas + 64, ss + 128, invN1);
    apply_kernel<<<a1n, 256>>>(bufC, ss + 128, nullptr, bufD, N1 * 8);   // bufD = x1

    // res block 1
    mma_conv_kernel<27><<<g1, 256, sm27>>>(bufD, nbr1, (const uint4 *)B_r1a, bufC, stats + 192, N1);
    finalize_kernel<<<1, 32>>>(stats + 192, gammas + 96, betas + 96, ss + 192, invN1);
    apply_kernel<<<a1n, 256>>>(bufC, ss + 192, nullptr, bufA, N1 * 8);

    mma_conv_kernel<27><<<g1, 256, sm27>>>(bufA, nbr1, (const uint4 *)B_r1b, bufC, stats + 256, N1);
    finalize_kernel<<<1, 32>>>(stats + 256, gammas + 128, betas + 128, ss + 256, invN1);
    apply_kernel<<<a1n, 256>>>(bufC, ss + 256, bufD, bufB, N1 * 8);      // bufB = x1'

    // res block 2
    mma_conv_kernel<27><<<g1, 256, sm27>>>(bufB, nbr1, (const uint4 *)B_r2a, bufC, stats + 320, N1);
    finalize_kernel<<<1, 32>>>(stats + 320, gammas + 160, betas + 160, ss + 320, invN1);
    apply_kernel<<<a1n, 256>>>(bufC, ss + 320, nullptr, bufA, N1 * 8);

    mma_conv_kernel<27><<<g1, 256, sm27>>>(bufA, nbr1, (const uint4 *)B_r2b, bufC, stats + 384, N1);
    finalize_kernel<<<1, 32>>>(stats + 384, gammas + 192, betas + 192, ss + 384, invN1);
    apply_kernel<<<a1n, 256>>>(bufC, ss + 384, bufB, out, N1 * 8);       // final output
}

// round 6
// speedup vs baseline: 3.5266x; 1.0180x over previous
#include <cuda_runtime.h>
#include <cuda_bf16.h>
#include <cstdint>

typedef unsigned long long u64;
typedef unsigned int u32;

// ---------------------------------------------------------------------------
// Scratch (no allocations allowed). Activation buffers hold either raw fp32
// rows or split-bf16 rows (16 u32 hi pairs + 16 u32 lo pairs) — same bytes.
// ---------------------------------------------------------------------------
#define MAXN 450000
__device__ float g_bufA[(size_t)MAXN * 32];
__device__ float g_bufB[(size_t)MAXN * 32];
__device__ float g_bufC[(size_t)MAXN * 32];
__device__ float g_bufD[(size_t)MAXN * 32];
__device__ float g_stats[7 * 64];   // per layer: sum[32], sumsq[32]
__device__ float g_ss[7 * 64];      // per layer: scale[32], shift[32]
// Fragment-ordered split-bf16 weights: per layer K*1024 u32 (hi K*512 then lo)
__device__ u32 g_Bw[5 * 27 * 1024 + 8 * 1024];
__device__ u32 g_Bs1[2 * 1792];      // stem1: 7 groups * 256 u32 hi + lo

// ---------------------------------------------------------------------------
// helpers
// ---------------------------------------------------------------------------
// pack: low half <- a, high half <- b
__device__ __forceinline__ u32 packbf(float a, float b) {
    u32 r;
    asm("cvt.rn.bf16x2.f32 %0, %1, %2;" : "=r"(r) : "f"(b), "f"(a));
    return r;
}
__device__ __forceinline__ float lof(u32 h) { return __uint_as_float(h << 16); }
__device__ __forceinline__ float hif(u32 h) { return __uint_as_float(h & 0xFFFF0000u); }
__device__ __forceinline__ void cvtp(float x, float y, u32 &h, u32 &l) {
    h = packbf(x, y);
    l = packbf(x - lof(h), y - hif(h));
}
__device__ __forceinline__ void mma16816(float *d, const u32 *a, u32 b0, u32 b1) {
    asm volatile(
        "mma.sync.aligned.m16n8k16.row.col.f32.bf16.bf16.f32 "
        "{%0,%1,%2,%3}, {%4,%5,%6,%7}, {%8,%9}, {%0,%1,%2,%3};"
        : "+f"(d[0]), "+f"(d[1]), "+f"(d[2]), "+f"(d[3])
        : "r"(a[0]), "r"(a[1]), "r"(a[2]), "r"(a[3]), "r"(b0), "r"(b1));
}
// 12 MMAs: one kc pass (hh, lh, hl) over 4 nc
__device__ __forceinline__ void mma_pass(float *acc, const u32 *ah, const u32 *al,
                                         uint4 H0, uint4 H1, uint4 L0, uint4 L1) {
    mma16816(acc + 0,  ah, H0.x, H0.y);
    mma16816(acc + 0,  al, H0.x, H0.y);
    mma16816(acc + 0,  ah, L0.x, L0.y);
    mma16816(acc + 4,  ah, H0.z, H0.w);
    mma16816(acc + 4,  al, H0.z, H0.w);
    mma16816(acc + 4,  ah, L0.z, L0.w);
    mma16816(acc + 8,  ah, H1.x, H1.y);
    mma16816(acc + 8,  al, H1.x, H1.y);
    mma16816(acc + 8,  ah, L1.x, L1.y);
    mma16816(acc + 12, ah, H1.z, H1.w);
    mma16816(acc + 12, al, H1.z, H1.w);
    mma16816(acc + 12, ah, L1.z, L1.w);
}

// ---------------------------------------------------------------------------
// Weight prep (generic C32 layers): physical channel for (kc,m,h,j) = 8m+4kc+2h+j
// layout per tap: [kc][c2][lane][e] (512 u32); hi block [K*512], lo at +K*512.
// ---------------------------------------------------------------------------
__global__ void prep_weights(const float *__restrict__ W, u32 *__restrict__ out, int K)
{
    int t = blockIdx.x * 256 + threadIdx.x;
    if (t >= K * 512) return;
    int tap  = t >> 9;
    int r    = t & 511;
    int kc   = r >> 8;
    int c2   = (r >> 7) & 1;
    int lane = (r >> 2) & 31;
    int e    = r & 3;
    int nc   = c2 * 2 + (e >> 1);
    int h    = e & 1;
    int mm   = lane & 3;
    int n    = nc * 8 + (lane >> 2);
    int k0   = 8 * mm + 4 * kc + 2 * h;
    float w0 = W[((size_t)tap * 32 + k0) * 32 + n];
    float w1 = W[((size_t)tap * 32 + k0 + 1) * 32 + n];
    u32 hh = packbf(w0, w1);
    u32 ll = packbf(w0 - lof(hh), w1 - hif(hh));
    out[t] = hh;
    out[(size_t)K * 512 + t] = ll;
}

// stem1 prep: 27 taps x 4 ci packed as 7 groups of K=16 (4 taps).
__global__ void prep_stem1(const float *__restrict__ W, u32 *__restrict__ out)
{
    int t = blockIdx.x * 256 + threadIdx.x;
    if (t >= 1792) return;
    int g    = t >> 8;
    int r    = t & 255;
    int c2   = r >> 7;
    int lane = (r >> 2) & 31;
    int e    = r & 3;
    int nc   = c2 * 2 + (e >> 1);
    int h    = e & 1;
    int mm   = lane & 3;
    int n    = nc * 8 + (lane >> 2);
    int k0   = 2 * mm + 8 * h;
    int tap  = 4 * g + (k0 >> 2);
    int ci   = k0 & 3;
    float w0 = (tap < 27) ? W[((size_t)tap * 4 + ci) * 32 + n] : 0.f;
    float w1 = (tap < 27) ? W[((size_t)tap * 4 + ci + 1) * 32 + n] : 0.f;
    u32 hh = packbf(w0, w1);
    u32 ll = packbf(w0 - lof(hh), w1 - hif(hh));
    out[t] = hh;
    out[1792 + t] = ll;
}

// ---------------------------------------------------------------------------
// Generic HMMA gather-spconv (CI=32, split-bf16 input rows) + BN partial sums.
// 256 threads, 8 warps, 32 rows/warp = 256 rows/CTA. Weights in smem.
// Input row layout (u32[32]): [0..15] hi pairs (ch 2j,2j+1), [16..31] lo pairs.
// ---------------------------------------------------------------------------
template <int K>
__global__ void __launch_bounds__(256, 2) mma_conv_kernel(
    const u32 *__restrict__ feat,     // split rows [*, 32 u32]
    const int *__restrict__ nbr,      // [K, N]
    const uint4 *__restrict__ Wf,     // fragment weights, K*256 uint4 (hi+lo)
    float      *__restrict__ out,     // [N, 32] raw pre-BN
    float      *__restrict__ stats,   // [64]
    int N)
{
    extern __shared__ u32 sW[];       // K*1024 u32
    __shared__ float s_sum[64];
    const int tid = threadIdx.x, wid = tid >> 5, lane = tid & 31;

    {
        uint4 *dst = (uint4 *)sW;
#pragma unroll 4
        for (int i = tid; i < K * 256; i += 256) dst[i] = __ldg(Wf + i);
    }
    if (tid < 64) s_sum[tid] = 0.f;
    __syncthreads();

    const int rowbase = (blockIdx.x * 8 + wid) * 32;
    const int m = lane & 3;
    const int rq = lane >> 2;
    int r0 = rowbase + rq;

    float acc[32];
#pragma unroll
    for (int i = 0; i < 32; i++) acc[i] = 0.f;

    int idxc[4], idxn[4];
#pragma unroll
    for (int q = 0; q < 4; q++) {
        int rr = r0 + q * 8;
        idxc[q] = (rr < N) ? __ldg(nbr + rr) : -1;
    }

#pragma unroll 1
    for (int k = 0; k < K; k++) {
#pragma unroll
        for (int q = 0; q < 4; q++) {
            int rr = r0 + q * 8;
            idxn[q] = (k + 1 < K && rr < N) ? __ldg(nbr + (size_t)(k + 1) * N + rr) : -1;
        }
        int anyv = (idxc[0] >= 0) | (idxc[1] >= 0) | (idxc[2] >= 0) | (idxc[3] >= 0);
        if (__ballot_sync(0xffffffffu, anyv)) {
            // gather: fragments directly (hi uint4 + lo uint4 per row)
            uint4 H[4], L[4];
#pragma unroll
            for (int q = 0; q < 4; q++) {
                if (idxc[q] >= 0) {
                    const uint4 *p = (const uint4 *)(feat + (size_t)idxc[q] * 32);
                    H[q] = __ldg(p + m);
                    L[q] = __ldg(p + 4 + m);
                } else {
                    H[q] = make_uint4(0u, 0u, 0u, 0u);
                    L[q] = make_uint4(0u, 0u, 0u, 0u);
                }
            }
            const u32 hb = (u32)k * 512u;
            const u32 lb = (u32)K * 512u + (u32)k * 512u;
            uint4 H00 = ((const uint4 *)(sW + hb))[lane];
            uint4 H01 = ((const uint4 *)(sW + hb + 128))[lane];
            uint4 H10 = ((const uint4 *)(sW + hb + 256))[lane];
            uint4 H11 = ((const uint4 *)(sW + hb + 384))[lane];
            uint4 L00 = ((const uint4 *)(sW + lb))[lane];
            uint4 L01 = ((const uint4 *)(sW + lb + 128))[lane];
            uint4 L10 = ((const uint4 *)(sW + lb + 256))[lane];
            uint4 L11 = ((const uint4 *)(sW + lb + 384))[lane];

#pragma unroll
            for (int b = 0; b < 2; b++) {
                u32 ah0[4] = { H[2*b].x, H[2*b+1].x, H[2*b].y, H[2*b+1].y };
                u32 al0[4] = { L[2*b].x, L[2*b+1].x, L[2*b].y, L[2*b+1].y };
                u32 ah1[4] = { H[2*b].z, H[2*b+1].z, H[2*b].w, H[2*b+1].w };
                u32 al1[4] = { L[2*b].z, L[2*b+1].z, L[2*b].w, L[2*b+1].w };
                mma_pass(acc + b * 16, ah0, al0, H00, H01, L00, L01);   // kc0
                mma_pass(acc + b * 16, ah1, al1, H10, H11, L10, L11);   // kc1
            }
        }
#pragma unroll
        for (int q = 0; q < 4; q++) idxc[q] = idxn[q];
    }

    // ---- epilogue: store raw rows; cols = nc*8 + m*2
#pragma unroll
    for (int b = 0; b < 2; b++) {
        int ra = rowbase + b * 16 + rq;
        int rb = ra + 8;
        if (ra < N) {
            float *o = out + (size_t)ra * 32 + m * 2;
#pragma unroll
            for (int nc = 0; nc < 4; nc++)
                *(float2 *)(o + nc * 8) = make_float2(acc[b * 16 + nc * 4], acc[b * 16 + nc * 4 + 1]);
        }
        if (rb < N) {
            float *o = out + (size_t)rb * 32 + m * 2;
#pragma unroll
            for (int nc = 0; nc < 4; nc++)
                *(float2 *)(o + nc * 8) = make_float2(acc[b * 16 + nc * 4 + 2], acc[b * 16 + nc * 4 + 3]);
        }
    }

    // ---- BN partial sums
#pragma unroll
    for (int nc = 0; nc < 4; nc++) {
#pragma unroll
        for (int j = 0; j < 2; j++) {
            float a0 = acc[nc * 4 + j], a1 = acc[nc * 4 + 2 + j];
            float a2 = acc[16 + nc * 4 + j], a3 = acc[16 + nc * 4 + 2 + j];
            float s = (a0 + a1) + (a2 + a3);
            float q = (a0 * a0 + a1 * a1) + (a2 * a2 + a3 * a3);
#pragma unroll
            for (int o = 16; o >= 4; o >>= 1) {
                s += __shfl_xor_sync(0xffffffffu, s, o);
                q += __shfl_xor_sync(0xffffffffu, q, o);
            }
            if (lane < 4) {
                atomicAdd(&s_sum[nc * 8 + 2 * lane + j], s);
                atomicAdd(&s_sum[32 + nc * 8 + 2 * lane + j], q);
            }
        }
    }
    __syncthreads();
    if (tid < 64) atomicAdd(&stats[tid], s_sum[tid]);
}

// ---------------------------------------------------------------------------
// stem1: CIN=4 fp32 input, 27 taps packed as 7 MMA K-groups of 4 taps.
// ---------------------------------------------------------------------------
__global__ void __launch_bounds__(256, 2) stem1_kernel(
    const float *__restrict__ feat,   // [N, 4]
    const int   *__restrict__ nbr,    // [27, N]
    const u32   *__restrict__ Wf,     // 2*1792 u32
    float       *__restrict__ out,    // [N, 32] raw
    float       *__restrict__ stats,
    int N)
{
    __shared__ u32 sW[3584];
    __shared__ float s_sum[64];
    const int tid = threadIdx.x, wid = tid >> 5, lane = tid & 31;

#pragma unroll 2
    for (int i = tid; i < 896; i += 256) ((uint4 *)sW)[i] = __ldg((const uint4 *)Wf + i);
    if (tid < 64) s_sum[tid] = 0.f;
    __syncthreads();

    const int rowbase = (blockIdx.x * 8 + wid) * 32;
    const int m = lane & 3;
    const int rq = lane >> 2;
    const int ci0 = (m & 1) * 2;
    const int tA0 = m >> 1;

    float acc[32];
#pragma unroll
    for (int i = 0; i < 32; i++) acc[i] = 0.f;

#pragma unroll 1
    for (int g = 0; g < 7; g++) {
        const int tA = 4 * g + tA0;
        const int tB = tA + 2;
        float2 fA[4], fB[4];
#pragma unroll
        for (int q = 0; q < 4; q++) {
            int rr = rowbase + q * 8 + rq;
            int iA = (rr < N) ? __ldg(nbr + (size_t)tA * N + rr) : -1;
            int iB = (rr < N && tB < 27) ? __ldg(nbr + (size_t)tB * N + rr) : -1;
            fA[q] = (iA >= 0) ? __ldg((const float2 *)(feat + (size_t)iA * 4 + ci0))
                              : make_float2(0.f, 0.f);
            fB[q] = (iB >= 0) ? __ldg((const float2 *)(feat + (size_t)iB * 4 + ci0))
                              : make_float2(0.f, 0.f);
        }
        uint4 H0 = ((const uint4 *)(sW + g * 256))[lane];
        uint4 H1 = ((const uint4 *)(sW + g * 256 + 128))[lane];
        uint4 L0 = ((const uint4 *)(sW + 1792 + g * 256))[lane];
        uint4 L1 = ((const uint4 *)(sW + 1792 + g * 256 + 128))[lane];
#pragma unroll
        for (int b = 0; b < 2; b++) {
            u32 ah[4], al[4];
            cvtp(fA[2 * b].x,     fA[2 * b].y,     ah[0], al[0]);
            cvtp(fA[2 * b + 1].x, fA[2 * b + 1].y, ah[1], al[1]);
            cvtp(fB[2 * b].x,     fB[2 * b].y,     ah[2], al[2]);
            cvtp(fB[2 * b + 1].x, fB[2 * b + 1].y, ah[3], al[3]);
            mma_pass(acc + b * 16, ah, al, H0, H1, L0, L1);
        }
    }

#pragma unroll
    for (int b = 0; b < 2; b++) {
        int ra = rowbase + b * 16 + rq;
        int rb = ra + 8;
        if (ra < N) {
            float *o = out + (size_t)ra * 32 + m * 2;
#pragma unroll
            for (int nc = 0; nc < 4; nc++)
                *(float2 *)(o + nc * 8) = make_float2(acc[b * 16 + nc * 4], acc[b * 16 + nc * 4 + 1]);
        }
        if (rb < N) {
            float *o = out + (size_t)rb * 32 + m * 2;
#pragma unroll
            for (int nc = 0; nc < 4; nc++)
                *(float2 *)(o + nc * 8) = make_float2(acc[b * 16 + nc * 4 + 2], acc[b * 16 + nc * 4 + 3]);
        }
    }
#pragma unroll
    for (int nc = 0; nc < 4; nc++) {
#pragma unroll
        for (int j = 0; j < 2; j++) {
            float a0 = acc[nc * 4 + j], a1 = acc[nc * 4 + 2 + j];
            float a2 = acc[16 + nc * 4 + j], a3 = acc[16 + nc * 4 + 2 + j];
            float s = (a0 + a1) + (a2 + a3);
            float q = (a0 * a0 + a1 * a1) + (a2 * a2 + a3 * a3);
#pragma unroll
            for (int o = 16; o >= 4; o >>= 1) {
                s += __shfl_xor_sync(0xffffffffu, s, o);
                q += __shfl_xor_sync(0xffffffffu, q, o);
            }
            if (lane < 4) {
                atomicAdd(&s_sum[nc * 8 + 2 * lane + j], s);
                atomicAdd(&s_sum[32 + nc * 8 + 2 * lane + j], q);
            }
        }
    }
    __syncthreads();
    if (tid < 64) atomicAdd(&stats[tid], s_sum[tid]);
}

// ---------------------------------------------------------------------------
// BN finalize / apply / zero
// ---------------------------------------------------------------------------
__global__ void finalize_kernel(const float *__restrict__ stats,
                                const float *__restrict__ gamma,
                                const float *__restrict__ beta,
                                float *__restrict__ ss, float invN)
{
    int c = threadIdx.x;
    float mu  = stats[c] * invN;
    float var = stats[32 + c] * invN - mu * mu;
    float s = rsqrtf(var + 1e-5f) * gamma[c];
    ss[c] = s;
    ss[32 + c] = beta[c] - mu * s;
}

// apply: y = relu(x*sc+sh [+ res(split)]), write split rows. 4 lanes/row.
__global__ void apply_split_kernel(const float *__restrict__ x,
                                   const float *__restrict__ ss,
                                   const u32 *__restrict__ res,
                                   u32 *__restrict__ out, int n)
{
    int i = blockIdx.x * blockDim.x + threadIdx.x;
    if (i >= n) return;
    int row = i >> 2, m = i & 3;
    const float4 *px = (const float4 *)(x + (size_t)row * 32 + m * 8);
    float4 v0 = __ldg(px), v1 = __ldg(px + 1);
    float4 sc0 = ((const float4 *)ss)[2 * m], sc1 = ((const float4 *)ss)[2 * m + 1];
    float4 sh0 = ((const float4 *)(ss + 32))[2 * m], sh1 = ((const float4 *)(ss + 32))[2 * m + 1];
    float o0 = fmaf(v0.x, sc0.x, sh0.x), o1 = fmaf(v0.y, sc0.y, sh0.y);
    float o2 = fmaf(v0.z, sc0.z, sh0.z), o3 = fmaf(v0.w, sc0.w, sh0.w);
    float o4 = fmaf(v1.x, sc1.x, sh1.x), o5 = fmaf(v1.y, sc1.y, sh1.y);
    float o6 = fmaf(v1.z, sc1.z, sh1.z), o7 = fmaf(v1.w, sc1.w, sh1.w);
    if (res) {
        const uint4 *pr = (const uint4 *)(res + (size_t)row * 32);
        uint4 rh = __ldg(pr + m), rl = __ldg(pr + 4 + m);
        o0 += lof(rh.x) + lof(rl.x);  o1 += hif(rh.x) + hif(rl.x);
        o2 += lof(rh.y) + lof(rl.y);  o3 += hif(rh.y) + hif(rl.y);
        o4 += lof(rh.z) + lof(rl.z);  o5 += hif(rh.z) + hif(rl.z);
        o6 += lof(rh.w) + lof(rl.w);  o7 += hif(rh.w) + hif(rl.w);
    }
    o0 = fmaxf(o0, 0.f); o1 = fmaxf(o1, 0.f); o2 = fmaxf(o2, 0.f); o3 = fmaxf(o3, 0.f);
    o4 = fmaxf(o4, 0.f); o5 = fmaxf(o5, 0.f); o6 = fmaxf(o6, 0.f); o7 = fmaxf(o7, 0.f);
    uint4 h, l;
    cvtp(o0, o1, h.x, l.x);
    cvtp(o2, o3, h.y, l.y);
    cvtp(o4, o5, h.z, l.z);
    cvtp(o6, o7, h.w, l.w);
    uint4 *po = (uint4 *)(out + (size_t)row * 32);
    po[m] = h;
    po[4 + m] = l;
}

// final apply: fp32 output rows (natural channel order)
__global__ void apply_final_kernel(const float *__restrict__ x,
                                   const float *__restrict__ ss,
                                   const u32 *__restrict__ res,
                                   float *__restrict__ out, int n)
{
    int i = blockIdx.x * blockDim.x + threadIdx.x;
    if (i >= n) return;
    int row = i >> 2, m = i & 3;
    const float4 *px = (const float4 *)(x + (size_t)row * 32 + m * 8);
    float4 v0 = __ldg(px), v1 = __ldg(px + 1);
    float4 sc0 = ((const float4 *)ss)[2 * m], sc1 = ((const float4 *)ss)[2 * m + 1];
    float4 sh0 = ((const float4 *)(ss + 32))[2 * m], sh1 = ((const float4 *)(ss + 32))[2 * m + 1];
    float4 a, b;
    a.x = fmaf(v0.x, sc0.x, sh0.x); a.y = fmaf(v0.y, sc0.y, sh0.y);
    a.z = fmaf(v0.z, sc0.z, sh0.z); a.w = fmaf(v0.w, sc0.w, sh0.w);
    b.x = fmaf(v1.x, sc1.x, sh1.x); b.y = fmaf(v1.y, sc1.y, sh1.y);
    b.z = fmaf(v1.z, sc1.z, sh1.z); b.w = fmaf(v1.w, sc1.w, sh1.w);
    if (res) {
        const uint4 *pr = (const uint4 *)(res + (size_t)row * 32);
        uint4 rh = __ldg(pr + m), rl = __ldg(pr + 4 + m);
        a.x += lof(rh.x) + lof(rl.x);  a.y += hif(rh.x) + hif(rl.x);
        a.z += lof(rh.y) + lof(rl.y);  a.w += hif(rh.y) + hif(rl.y);
        b.x += lof(rh.z) + lof(rl.z);  b.y += hif(rh.z) + hif(rl.z);
        b.z += lof(rh.w) + lof(rl.w);  b.w += hif(rh.w) + hif(rl.w);
    }
    a.x = fmaxf(a.x, 0.f); a.y = fmaxf(a.y, 0.f); a.z = fmaxf(a.z, 0.f); a.w = fmaxf(a.w, 0.f);
    b.x = fmaxf(b.x, 0.f); b.y = fmaxf(b.y, 0.f); b.z = fmaxf(b.z, 0.f); b.w = fmaxf(b.w, 0.f);
    float4 *po = (float4 *)(out + (size_t)row * 32 + m * 8);
    po[0] = a;
    po[1] = b;
}

__global__ void zero_kernel(float *p, int n)
{
    int i = blockIdx.x * blockDim.x + threadIdx.x;
    if (i < n) p[i] = 0.f;
}

// ---------------------------------------------------------------------------
extern "C" void kernel_launch(void *const *d_in, const int *in_sizes, int n_in,
                              void *d_out, int out_size)
{
    const float *vf     = (const float *)d_in[0];
    const float *Wstem1 = (const float *)d_in[1];
    const float *Wstem2 = (const float *)d_in[2];
    const float *Wdown  = (const float *)d_in[3];
    const float *Wr1a   = (const float *)d_in[4];
    const float *Wr1b   = (const float *)d_in[5];
    const float *Wr2a   = (const float *)d_in[6];
    const float *Wr2b   = (const float *)d_in[7];
    const float *gammas = (const float *)d_in[8];
    const float *betas  = (const float *)d_in[9];
    const int *nbr0  = (const int *)d_in[10];
    const int *down1 = (const int *)d_in[11];
    const int *nbr1  = (const int *)d_in[12];

    int N0 = in_sizes[10] / 27;
    int N1 = in_sizes[11] / 8;

    float *bufA, *bufB, *bufC, *bufD, *stats, *ss;
    u32 *Bw, *Bs1;
    cudaGetSymbolAddress((void **)&bufA, g_bufA);
    cudaGetSymbolAddress((void **)&bufB, g_bufB);
    cudaGetSymbolAddress((void **)&bufC, g_bufC);
    cudaGetSymbolAddress((void **)&bufD, g_bufD);
    cudaGetSymbolAddress((void **)&stats, g_stats);
    cudaGetSymbolAddress((void **)&ss, g_ss);
    cudaGetSymbolAddress((void **)&Bw, g_Bw);
    cudaGetSymbolAddress((void **)&Bs1, g_Bs1);

    u32 *uA = (u32 *)bufA, *uB = (u32 *)bufB, *uD = (u32 *)bufD;

    const size_t L27 = (size_t)27 * 1024;
    u32 *B_stem2 = Bw + 0 * L27;
    u32 *B_r1a   = Bw + 1 * L27;
    u32 *B_r1b   = Bw + 2 * L27;
    u32 *B_r2a   = Bw + 3 * L27;
    u32 *B_r2b   = Bw + 4 * L27;
    u32 *B_down  = Bw + 5 * L27;

    size_t sm27 = (size_t)27 * 4096;   // 110592 B
    size_t sm8  = (size_t)8 * 4096;    // 32768 B
    cudaFuncSetAttribute(mma_conv_kernel<27>,
                         cudaFuncAttributeMaxDynamicSharedMemorySize, (int)sm27);
    cudaFuncSetAttribute(mma_conv_kernel<8>,
                         cudaFuncAttributeMaxDynamicSharedMemorySize, (int)sm8);

    int g0  = (N0 + 255) / 256;
    int g1  = (N1 + 255) / 256;
    int a0n = (N0 * 4 + 255) / 256;
    int a1n = (N1 * 4 + 255) / 256;
    float invN0 = 1.f / (float)N0;
    float invN1 = 1.f / (float)N1;
    float *out = (float *)d_out;

    prep_weights<<<54, 256>>>(Wstem2, B_stem2, 27);
    prep_weights<<<54, 256>>>(Wr1a,   B_r1a,   27);
    prep_weights<<<54, 256>>>(Wr1b,   B_r1b,   27);
    prep_weights<<<54, 256>>>(Wr2a,   B_r2a,   27);
    prep_weights<<<54, 256>>>(Wr2b,   B_r2b,   27);
    prep_weights<<<16, 256>>>(Wdown,  B_down,  8);
    prep_stem1<<<7, 256>>>(Wstem1, Bs1);

    zero_kernel<<<1, 448>>>(stats, 448);

    // stem1: raw -> bufA; apply -> split bufB
    stem1_kernel<<<g0, 256>>>(vf, nbr0, Bs1, bufA, stats + 0, N0);
    finalize_kernel<<<1, 32>>>(stats + 0, gammas + 0, betas + 0, ss + 0, invN0);
    apply_split_kernel<<<a0n, 256>>>(bufA, ss + 0, nullptr, uB, N0 * 4);

    // stem2: split bufB -> raw bufA; apply -> split bufB
    mma_conv_kernel<27><<<g0, 256, sm27>>>(uB, nbr0, (const uint4 *)B_stem2, bufA, stats + 64, N0);
    finalize_kernel<<<1, 32>>>(stats + 64, gammas + 32, betas + 32, ss + 64, invN0);
    apply_split_kernel<<<a0n, 256>>>(bufA, ss + 64, nullptr, uB, N0 * 4);

    // down: split bufB -> raw bufC; apply -> split bufD (x1)
    mma_conv_kernel<8><<<g1, 256, sm8>>>(uB, down1, (const uint4 *)B_down, bufC, stats + 128, N1);
    finalize_kernel<<<1, 32>>>(stats + 128, gammas + 64, betas + 64, ss + 128, invN1);
    apply_split_kernel<<<a1n, 256>>>(bufC, ss + 128, nullptr, uD, N1 * 4);

    // res block 1
    mma_conv_kernel<27><<<g1, 256, sm27>>>(uD, nbr1, (const uint4 *)B_r1a, bufC, stats + 192, N1);
    finalize_kernel<<<1, 32>>>(stats + 192, gammas + 96, betas + 96, ss + 192, invN1);
    apply_split_kernel<<<a1n, 256>>>(bufC, ss + 192, nullptr, uA, N1 * 4);        // h

    mma_conv_kernel<27><<<g1, 256, sm27>>>(uA, nbr1, (const uint4 *)B_r1b, bufC, stats + 256, N1);
    finalize_kernel<<<1, 32>>>(stats + 256, gammas + 128, betas + 128, ss + 256, invN1);
    apply_split_kernel<<<a1n, 256>>>(bufC, ss + 256, uD, uB, N1 * 4);             // x1' = relu(h+x1)

    // res block 2
    mma_conv_kernel<27><<<g1, 256, sm27>>>(uB, nbr1, (const uint4 *)B_r2a, bufC, stats + 320, N1);
    finalize_kernel<<<1, 32>>>(stats + 320, gammas + 160, betas + 160, ss + 320, invN1);
    apply_split_kernel<<<a1n, 256>>>(bufC, ss + 320, nullptr, uA, N1 * 4);

    mma_conv_kernel<27><<<g1, 256, sm27>>>(uA, nbr1, (const uint4 *)B_r2b, bufC, stats + 384, N1);
    finalize_kernel<<<1, 32>>>(stats + 384, gammas + 192, betas + 192, ss + 384, invN1);
    apply_final_kernel<<<a1n, 256>>>(bufC, ss + 384, uB, out, N1 * 4);            // fp32 output
}